// round 1
// baseline (speedup 1.0000x reference)
#include <cuda_runtime.h>
#include <cstdint>

// ----------------------------------------------------------------------------
// BaseGR hetero-SAGE on GB300.
// Math exploited: hg (group embeddings) are zeroed -> layer1 group-side terms
// vanish; final output depends only on layer2 'og' -> ou2/oi2 never computed.
// Aggregation done via per-call CSR build (count/scan/bucket) + gather-side
// segment-mean (no fp32 atomics). GEMMs: fp32 SIMT with packed fma.rn.f32x2.
// ----------------------------------------------------------------------------

#define NG 5000
#define NU 100000
#define NI 20000
#define H 128
#define HH (H*H)
#define E_UG 300000
#define E_UI 600000
#define E_GI 200000

// ---------------- float scratch (one big __device__ array) ------------------
#define OF_HU  0
#define OF_HI  (OF_HU  + NU*H)
#define OF_AIU (OF_HI  + NI*H)
#define OF_AUI (OF_AIU + NU*H)
#define OF_AUG (OF_AUI + NI*H)
#define OF_AIG (OF_AUG + NG*H)
#define OF_HU1 (OF_AIG + NG*H)
#define OF_HI1 (OF_HU1 + NU*H)
#define OF_HG1 (OF_HI1 + NI*H)
#define OF_BUG (OF_HG1 + NG*H)
#define OF_BIG (OF_BUG + NG*H)
#define OF_REP (OF_BIG + NG*H)
#define OF_WC  (OF_REP + NG*H)
#define OF_BC  (OF_WC  + 3*HH)
#define F_TOTAL (OF_BC + 4*H)

__device__ float g_f[F_TOTAL];

// ---------------- int scratch: counts first (single memset region) ----------
#define OI_CNT_G1 0
#define OI_CNT_G2 (OI_CNT_G1 + NG)
#define OI_CNT_U  (OI_CNT_G2 + NG)
#define OI_CNT_I  (OI_CNT_U  + NU)
#define CNT_TOTAL (OI_CNT_I  + NI)
#define OI_RP_G1  CNT_TOTAL
#define OI_RP_G2  (OI_RP_G1 + NG + 1)
#define OI_RP_U   (OI_RP_G2 + NG + 1)
#define OI_RP_I   (OI_RP_U  + NU + 1)
#define OI_CUR_G1 (OI_RP_I  + NI + 1)
#define OI_CUR_G2 (OI_CUR_G1 + NG)
#define OI_CUR_U  (OI_CUR_G2 + NG)
#define OI_CUR_I  (OI_CUR_U  + NU)
#define OI_COL_G1 (OI_CUR_I  + NI)
#define OI_COL_G2 (OI_COL_G1 + E_UG)
#define OI_COL_U  (OI_COL_G2 + E_GI)
#define OI_COL_I  (OI_COL_U  + E_UI)
#define I_TOTAL   (OI_COL_I  + E_UI)

__device__ int g_i[I_TOTAL];

// ---------------------------------------------------------------------------
// gather embedding rows: out[r] = emb[x[r]]   (H floats = 32 float4 per row)
__global__ void k_gather(const float* __restrict__ emb, const int* __restrict__ x,
                         float* __restrict__ out, int n)
{
    int t = blockIdx.x * blockDim.x + threadIdx.x;
    if (t >= n * 32) return;
    int r = t >> 5, c = t & 31;
    ((float4*)out)[t] = ((const float4*)emb)[(size_t)x[r] * 32 + c];
}

// count destinations
__global__ void k_count(const int* __restrict__ dst, int E, int* __restrict__ cnt)
{
    int e = blockIdx.x * blockDim.x + threadIdx.x;
    if (e < E) atomicAdd(&cnt[dst[e]], 1);
}

// single-block exclusive scan -> row_ptr[0..n], cursor copy
__global__ void k_scan(const int* __restrict__ cnt, int* __restrict__ row_ptr,
                       int* __restrict__ cursor, int n)
{
    __shared__ int ssum[1024];
    const int t = threadIdx.x;
    const int chunk = (n + 1023) / 1024;
    int beg = t * chunk;
    int end = beg + chunk; if (end > n) end = n;
    if (beg > n) beg = n;
    int s = 0;
    for (int i = beg; i < end; i++) s += cnt[i];
    ssum[t] = s;
    __syncthreads();
    // Hillis-Steele inclusive scan
    for (int off = 1; off < 1024; off <<= 1) {
        int v = (t >= off) ? ssum[t - off] : 0;
        __syncthreads();
        ssum[t] += v;
        __syncthreads();
    }
    int prefix = (t == 0) ? 0 : ssum[t - 1];
    for (int i = beg; i < end; i++) {
        row_ptr[i] = prefix;
        cursor[i]  = prefix;
        prefix += cnt[i];
    }
    if (t == 1023) row_ptr[n] = ssum[1023];
}

// scatter edges into CSR buckets
__global__ void k_bucket(const int* __restrict__ dst, const int* __restrict__ src,
                         int E, int* __restrict__ cursor, int* __restrict__ col)
{
    int e = blockIdx.x * blockDim.x + threadIdx.x;
    if (e >= E) return;
    int p = atomicAdd(&cursor[dst[e]], 1);
    col[p] = src[e];
}

// gather-side segment mean: one warp per destination row
__global__ void k_agg(const int* __restrict__ rp, const int* __restrict__ col,
                      const float* __restrict__ feat, float* __restrict__ out, int nrows)
{
    int w = (int)((blockIdx.x * blockDim.x + threadIdx.x) >> 5);
    int lane = threadIdx.x & 31;
    if (w >= nrows) return;
    int beg = rp[w], end = rp[w + 1];
    float4 acc = make_float4(0.f, 0.f, 0.f, 0.f);
    const float4* fv = (const float4*)feat;
    for (int e = beg; e < end; e++) {
        int s = __ldg(&col[e]);
        float4 v = __ldg(&fv[(size_t)s * 32 + lane]);
        acc.x += v.x; acc.y += v.y; acc.z += v.z; acc.w += v.w;
    }
    float inv = (end > beg) ? 1.f / (float)(end - beg) : 0.f;
    acc.x *= inv; acc.y *= inv; acc.z *= inv; acc.w *= inv;
    ((float4*)out)[(size_t)w * 32 + lane] = acc;
}

// combine self-loop weight matrices and biases (zero-group simplifications)
__global__ void k_wcomb(const float* __restrict__ W1r, const float* __restrict__ b1,
                        const float* __restrict__ W2r, const float* __restrict__ b2)
{
    int i = blockIdx.x * blockDim.x + threadIdx.x;
    float* Wc = g_f + OF_WC;
    float* bc = g_f + OF_BC;
    if (i < HH) {
        Wc[0*HH + i] = W1r[1*HH + i] + W1r[3*HH + i];  // users:  Wr1+Wr3
        Wc[1*HH + i] = W1r[2*HH + i] + W1r[4*HH + i];  // items:  Wr2+Wr4
        Wc[2*HH + i] = W2r[0*HH + i] + W2r[5*HH + i];  // groups: W2r0+W2r5
    }
    if (i < H) {
        bc[0*H + i] = b1[1*H + i] + b1[3*H + i];       // users L1
        bc[1*H + i] = b1[2*H + i] + b1[4*H + i];       // items L1
        bc[2*H + i] = b1[0*H + i] + b1[5*H + i];       // groups L1
        bc[3*H + i] = b2[0*H + i] + b2[5*H + i];       // groups L2
    }
}

// ---------------------------------------------------------------------------
// Fused GEMM: C[M,N] = act( A0[M,128]@W0[128,N] (+ A1@W1) + bias (+ C if acc) )
// W row stride = ldw. 128x128 tile, 256 threads, 8x8 micro-tile, BK=16,
// inner product via packed fma.rn.f32x2 (2x fp32 rate on sm_103a).
#define GEMM_ACC  1
#define GEMM_RELU 2

__global__ void __launch_bounds__(256)
k_gemm(const float* __restrict__ A0, const float* __restrict__ W0,
       const float* __restrict__ A1, const float* __restrict__ W1,
       const float* __restrict__ bias, float* __restrict__ C,
       int M, int N, int ldw, int flags)
{
    __shared__ float sA[16][128];   // [k][m] (transposed for contiguous m reads)
    __shared__ float sW[16][128];   // [k][n]
    const int tid = threadIdx.x;
    const int tx = tid & 15;        // 16 threads in N  -> 8 cols each
    const int ty = tid >> 4;        // 16 threads in M  -> 8 rows each
    const int m0 = blockIdx.y * 128;
    const int n0 = blockIdx.x * 128;

    unsigned long long acc2[8][4];  // 8 rows x 4 f32x2 pairs (8 cols)
#pragma unroll
    for (int i = 0; i < 8; i++)
#pragma unroll
        for (int j = 0; j < 4; j++) acc2[i][j] = 0ULL;

#pragma unroll 1
    for (int term = 0; term < 2; term++) {
        const float* A = term ? A1 : A0;
        const float* W = term ? W1 : W0;
        if (A == nullptr) break;
#pragma unroll 1
        for (int k0 = 0; k0 < H; k0 += 16) {
            // A tile load (zero-fill beyond M), store transposed
            {
                int l = tid;
#pragma unroll
                for (int r = 0; r < 2; r++, l += 256) {
                    int m = l >> 2;
                    int q = (l & 3) * 4;
                    float4 v = make_float4(0.f, 0.f, 0.f, 0.f);
                    if (m0 + m < M)
                        v = *(const float4*)(A + (size_t)(m0 + m) * H + k0 + q);
                    sA[q + 0][m] = v.x;
                    sA[q + 1][m] = v.y;
                    sA[q + 2][m] = v.z;
                    sA[q + 3][m] = v.w;
                }
            }
            // W tile load (zero-fill beyond N)
            {
                int l = tid;
#pragma unroll
                for (int r = 0; r < 2; r++, l += 256) {
                    int k  = l >> 5;
                    int nq = (l & 31) * 4;
                    float4 v = make_float4(0.f, 0.f, 0.f, 0.f);
                    if (n0 + nq < N)
                        v = *(const float4*)(W + (size_t)(k0 + k) * ldw + n0 + nq);
                    *(float4*)&sW[k][nq] = v;
                }
            }
            __syncthreads();
#pragma unroll
            for (int kk = 0; kk < 16; kk++) {
                float4 a0 = *(const float4*)&sA[kk][ty * 8];
                float4 a1 = *(const float4*)&sA[kk][ty * 8 + 4];
                ulonglong2 w0 = *(const ulonglong2*)&sW[kk][tx * 8];
                ulonglong2 w1 = *(const ulonglong2*)&sW[kk][tx * 8 + 4];
                unsigned long long B2[4] = { w0.x, w0.y, w1.x, w1.y };
                float ar[8] = { a0.x, a0.y, a0.z, a0.w, a1.x, a1.y, a1.z, a1.w };
                unsigned long long A2[8];
#pragma unroll
                for (int i = 0; i < 8; i++) {
                    unsigned int au = __float_as_uint(ar[i]);
                    asm("mov.b64 %0, {%1, %1};" : "=l"(A2[i]) : "r"(au));
                }
#pragma unroll
                for (int i = 0; i < 8; i++)
#pragma unroll
                    for (int j = 0; j < 4; j++)
                        asm("fma.rn.f32x2 %0, %1, %2, %0;"
                            : "+l"(acc2[i][j]) : "l"(A2[i]), "l"(B2[j]));
            }
            __syncthreads();
        }
    }

    const bool do_acc  = (flags & GEMM_ACC)  != 0;
    const bool do_relu = (flags & GEMM_RELU) != 0;
#pragma unroll
    for (int i = 0; i < 8; i++) {
        int m = m0 + ty * 8 + i;
        if (m >= M) continue;
        float vout[8];
#pragma unroll
        for (int j = 0; j < 4; j++) {
            union { unsigned long long u; float f[2]; } cv;
            cv.u = acc2[i][j];
            vout[2 * j + 0] = cv.f[0];
            vout[2 * j + 1] = cv.f[1];
        }
#pragma unroll
        for (int jq = 0; jq < 2; jq++) {
            int n = n0 + tx * 8 + jq * 4;
            if (n >= N) continue;   // N is a multiple of 4, float4 stays in-bounds
            float4 v = make_float4(vout[jq*4+0], vout[jq*4+1], vout[jq*4+2], vout[jq*4+3]);
            if (bias) {
                float4 b = *(const float4*)(bias + n);
                v.x += b.x; v.y += b.y; v.z += b.z; v.w += b.w;
            }
            float* cp = C + (size_t)m * N + n;
            if (do_acc) {
                float4 c = *(const float4*)cp;
                v.x += c.x; v.y += c.y; v.z += c.z; v.w += c.w;
            }
            if (do_relu) {
                v.x = fmaxf(v.x, 0.f); v.y = fmaxf(v.y, 0.f);
                v.z = fmaxf(v.z, 0.f); v.w = fmaxf(v.w, 0.f);
            }
            *(float4*)cp = v;
        }
    }
}

// ---------------------------------------------------------------------------
extern "C" void kernel_launch(void* const* d_in, const int* in_sizes, int n_in,
                              void* d_out, int out_size)
{
    const int*   x_user   = (const int*)  d_in[1];
    const int*   x_item   = (const int*)  d_in[2];
    const float* emb_user = (const float*)d_in[4];
    const float* emb_item = (const float*)d_in[5];
    const float* W1l      = (const float*)d_in[6];
    const float* W1r      = (const float*)d_in[7];
    const float* b1       = (const float*)d_in[8];
    const float* W2l      = (const float*)d_in[9];
    const float* W2r      = (const float*)d_in[10];
    const float* b2       = (const float*)d_in[11];
    const float* pred_W   = (const float*)d_in[12];
    const float* pred_b   = (const float*)d_in[13];
    const int*   ug_src   = (const int*)  d_in[14];
    const int*   ug_dst   = (const int*)  d_in[15];
    const int*   ui_src   = (const int*)  d_in[16];
    const int*   ui_dst   = (const int*)  d_in[17];
    const int*   gi_src   = (const int*)  d_in[18];
    const int*   gi_dst   = (const int*)  d_in[19];
    float* out = (float*)d_out;

    float* fb = nullptr; int* ib = nullptr;
    cudaGetSymbolAddress((void**)&fb, g_f);
    cudaGetSymbolAddress((void**)&ib, g_i);

    // zero the count arrays (contiguous region at the front of g_i)
    cudaMemsetAsync(ib + OI_CNT_G1, 0, (size_t)CNT_TOTAL * sizeof(int));

    // embedding gathers
    k_gather<<<(NU * 32 + 255) / 256, 256>>>(emb_user, x_user, fb + OF_HU, NU);
    k_gather<<<(NI * 32 + 255) / 256, 256>>>(emb_item, x_item, fb + OF_HI, NI);

    // degree counts
    k_count<<<(E_UG + 255) / 256, 256>>>(ug_dst, E_UG, ib + OI_CNT_G1);
    k_count<<<(E_GI + 255) / 256, 256>>>(gi_src, E_GI, ib + OI_CNT_G2);
    k_count<<<(E_UI + 255) / 256, 256>>>(ui_src, E_UI, ib + OI_CNT_U);
    k_count<<<(E_UI + 255) / 256, 256>>>(ui_dst, E_UI, ib + OI_CNT_I);

    // CSR row pointers + cursors
    k_scan<<<1, 1024>>>(ib + OI_CNT_G1, ib + OI_RP_G1, ib + OI_CUR_G1, NG);
    k_scan<<<1, 1024>>>(ib + OI_CNT_G2, ib + OI_RP_G2, ib + OI_CUR_G2, NG);
    k_scan<<<1, 1024>>>(ib + OI_CNT_U,  ib + OI_RP_U,  ib + OI_CUR_U,  NU);
    k_scan<<<1, 1024>>>(ib + OI_CNT_I,  ib + OI_RP_I,  ib + OI_CUR_I,  NI);

    // bucket edges (CSR col arrays)
    k_bucket<<<(E_UG + 255) / 256, 256>>>(ug_dst, ug_src, E_UG, ib + OI_CUR_G1, ib + OI_COL_G1);
    k_bucket<<<(E_GI + 255) / 256, 256>>>(gi_src, gi_dst, E_GI, ib + OI_CUR_G2, ib + OI_COL_G2);
    k_bucket<<<(E_UI + 255) / 256, 256>>>(ui_src, ui_dst, E_UI, ib + OI_CUR_U,  ib + OI_COL_U);
    k_bucket<<<(E_UI + 255) / 256, 256>>>(ui_dst, ui_src, E_UI, ib + OI_CUR_I,  ib + OI_COL_I);

    // combined weights / biases
    k_wcomb<<<(HH + 255) / 256, 256>>>(W1r, b1, W2r, b2);

    // layer-1 aggregations (gather-side segment means)
    k_agg<<<(NU + 7) / 8, 256>>>(ib + OI_RP_U,  ib + OI_COL_U,  fb + OF_HI, fb + OF_AIU, NU);
    k_agg<<<(NI + 7) / 8, 256>>>(ib + OI_RP_I,  ib + OI_COL_I,  fb + OF_HU, fb + OF_AUI, NI);
    k_agg<<<(NG + 7) / 8, 256>>>(ib + OI_RP_G1, ib + OI_COL_G1, fb + OF_HU, fb + OF_AUG, NG);
    k_agg<<<(NG + 7) / 8, 256>>>(ib + OI_RP_G2, ib + OI_COL_G2, fb + OF_HI, fb + OF_AIG, NG);

    // layer-1 GEMMs (fused 2-term + bias + relu)
    {
        dim3 g(1, (NU + 127) / 128);
        k_gemm<<<g, 256>>>(fb + OF_AIU, W1l + 3*HH, fb + OF_HU, fb + OF_WC + 0*HH,
                           fb + OF_BC + 0*H, fb + OF_HU1, NU, H, H, GEMM_RELU);
    }
    {
        dim3 g(1, (NI + 127) / 128);
        k_gemm<<<g, 256>>>(fb + OF_AUI, W1l + 2*HH, fb + OF_HI, fb + OF_WC + 1*HH,
                           fb + OF_BC + 1*H, fb + OF_HI1, NI, H, H, GEMM_RELU);
    }
    {
        dim3 g(1, (NG + 127) / 128);
        k_gemm<<<g, 256>>>(fb + OF_AUG, W1l + 0*HH, fb + OF_AIG, W1l + 5*HH,
                           fb + OF_BC + 2*H, fb + OF_HG1, NG, H, H, GEMM_RELU);
    }

    // layer-2 aggregations (reuse CSR, new features)
    k_agg<<<(NG + 7) / 8, 256>>>(ib + OI_RP_G1, ib + OI_COL_G1, fb + OF_HU1, fb + OF_BUG, NG);
    k_agg<<<(NG + 7) / 8, 256>>>(ib + OI_RP_G2, ib + OI_COL_G2, fb + OF_HI1, fb + OF_BIG, NG);

    // layer-2 og: rep = relu(Bug@W2l0 + hg1@(W2r0+W2r5) + Big@W2l5 + b20+b25)
    {
        dim3 g(1, (NG + 127) / 128);
        k_gemm<<<g, 256>>>(fb + OF_BUG, W2l + 0*HH, fb + OF_HG1, fb + OF_WC + 2*HH,
                           fb + OF_BC + 3*H, fb + OF_REP, NG, H, H, 0);
        k_gemm<<<g, 256>>>(fb + OF_BIG, W2l + 5*HH, nullptr, nullptr,
                           nullptr, fb + OF_REP, NG, H, H, GEMM_ACC | GEMM_RELU);
    }

    // final prediction GEMM: out[NG, NI] = rep @ pred_W + pred_b
    {
        dim3 g((NI + 127) / 128, (NG + 127) / 128);
        k_gemm<<<g, 256>>>(fb + OF_REP, pred_W, nullptr, nullptr,
                           pred_b, out, NG, NI, NI, 0);
    }
    (void)in_sizes; (void)n_in; (void)out_size;
}

// round 3
// speedup vs baseline: 1.2533x; 1.2533x over previous
#include <cuda_runtime.h>
#include <cuda_bf16.h>
#include <cstdint>

// ----------------------------------------------------------------------------
// BaseGR hetero-SAGE on GB300.
// R3: prediction GEMM on mma.sync.m16n8k16 bf16 (hi/lo 3-split, fp32 accum).
// tcgen05 is unavailable (harness PTX target is plain sm_103), so the tensor
// pipe is driven via classic warp-level MMA + ldmatrix.
// ----------------------------------------------------------------------------

#define NG 5000
#define NU 100000
#define NI 20000
#define H 128
#define HH (H*H)
#define E_UG 300000
#define E_UI 600000
#define E_GI 200000

// ---------------- float scratch ------------------
#define OF_HU  0
#define OF_HI  (OF_HU  + NU*H)
#define OF_AIU (OF_HI  + NI*H)
#define OF_AUI (OF_AIU + NU*H)
#define OF_AUG (OF_AUI + NI*H)
#define OF_AIG (OF_AUG + NG*H)
#define OF_HU1 (OF_AIG + NG*H)
#define OF_HI1 (OF_HU1 + NU*H)
#define OF_HG1 (OF_HI1 + NI*H)
#define OF_BUG (OF_HG1 + NG*H)
#define OF_BIG (OF_BUG + NG*H)
#define OF_REP (OF_BIG + NG*H)
#define OF_WC  (OF_REP + NG*H)
#define OF_BC  (OF_WC  + 3*HH)
#define F_TOTAL (OF_BC + 4*H)

__device__ float g_f[F_TOTAL];

// ---------------- bf16 scratch -----------------------------------------------
#define OB_AHI 0
#define OB_ALO (OB_AHI + NG*H)
#define OB_BHI (OB_ALO + NG*H)
#define OB_BLO (OB_BHI + NI*H)
#define B_TOTAL (OB_BLO + NI*H)

__device__ __nv_bfloat16 g_bf[B_TOTAL];

// ---------------- int scratch -------------------------------------------------
#define OI_CNT_G1 0
#define OI_CNT_G2 (OI_CNT_G1 + NG)
#define OI_CNT_U  (OI_CNT_G2 + NG)
#define OI_CNT_I  (OI_CNT_U  + NU)
#define CNT_TOTAL (OI_CNT_I  + NI)
#define OI_RP_G1  CNT_TOTAL
#define OI_RP_G2  (OI_RP_G1 + NG + 1)
#define OI_RP_U   (OI_RP_G2 + NG + 1)
#define OI_RP_I   (OI_RP_U  + NU + 1)
#define OI_CUR_G1 (OI_RP_I  + NI + 1)
#define OI_CUR_G2 (OI_CUR_G1 + NG)
#define OI_CUR_U  (OI_CUR_G2 + NG)
#define OI_CUR_I  (OI_CUR_U  + NU)
#define OI_COL_G1 (OI_CUR_I  + NI)
#define OI_COL_G2 (OI_COL_G1 + E_UG)
#define OI_COL_U  (OI_COL_G2 + E_GI)
#define OI_COL_I  (OI_COL_U  + E_UI)
#define I_TOTAL   (OI_COL_I  + E_UI)

__device__ int g_i[I_TOTAL];

// ======================= small helpers =======================================
__device__ __forceinline__ uint32_t smem_u32(const void* p) {
    uint32_t a;
    asm("{ .reg .u64 t; cvta.to.shared.u64 t, %1; cvt.u32.u64 %0, t; }"
        : "=r"(a) : "l"(p));
    return a;
}

#define LDSM4(r, addr) \
    asm volatile("ldmatrix.sync.aligned.m8n8.x4.shared.b16 {%0,%1,%2,%3}, [%4];" \
                 : "=r"((r)[0]), "=r"((r)[1]), "=r"((r)[2]), "=r"((r)[3]) \
                 : "r"(addr))

#define MMA_BF16(c, a, b0, b1) \
    asm volatile("mma.sync.aligned.m16n8k16.row.col.f32.bf16.bf16.f32 " \
                 "{%0,%1,%2,%3}, {%4,%5,%6,%7}, {%8,%9}, {%0,%1,%2,%3};" \
                 : "+f"((c)[0]), "+f"((c)[1]), "+f"((c)[2]), "+f"((c)[3]) \
                 : "r"((a)[0]), "r"((a)[1]), "r"((a)[2]), "r"((a)[3]), \
                   "r"(b0), "r"(b1))

// ======================= basic kernels (from R1) =============================
__global__ void k_gather(const float* __restrict__ emb, const int* __restrict__ x,
                         float* __restrict__ out, int n)
{
    int t = blockIdx.x * blockDim.x + threadIdx.x;
    if (t >= n * 32) return;
    int r = t >> 5, c = t & 31;
    ((float4*)out)[t] = ((const float4*)emb)[(size_t)x[r] * 32 + c];
}

__global__ void k_count(const int* __restrict__ dst, int E, int* __restrict__ cnt)
{
    int e = blockIdx.x * blockDim.x + threadIdx.x;
    if (e < E) atomicAdd(&cnt[dst[e]], 1);
}

__global__ void k_scan(const int* __restrict__ cnt, int* __restrict__ row_ptr,
                       int* __restrict__ cursor, int n)
{
    __shared__ int ssum[1024];
    const int t = threadIdx.x;
    const int chunk = (n + 1023) / 1024;
    int beg = t * chunk;
    int end = beg + chunk; if (end > n) end = n;
    if (beg > n) beg = n;
    int s = 0;
    for (int i = beg; i < end; i++) s += cnt[i];
    ssum[t] = s;
    __syncthreads();
    for (int off = 1; off < 1024; off <<= 1) {
        int v = (t >= off) ? ssum[t - off] : 0;
        __syncthreads();
        ssum[t] += v;
        __syncthreads();
    }
    int prefix = (t == 0) ? 0 : ssum[t - 1];
    for (int i = beg; i < end; i++) {
        row_ptr[i] = prefix;
        cursor[i]  = prefix;
        prefix += cnt[i];
    }
    if (t == 1023) row_ptr[n] = ssum[1023];
}

__global__ void k_bucket(const int* __restrict__ dst, const int* __restrict__ src,
                         int E, int* __restrict__ cursor, int* __restrict__ col)
{
    int e = blockIdx.x * blockDim.x + threadIdx.x;
    if (e >= E) return;
    int p = atomicAdd(&cursor[dst[e]], 1);
    col[p] = src[e];
}

__global__ void k_agg(const int* __restrict__ rp, const int* __restrict__ col,
                      const float* __restrict__ feat, float* __restrict__ out, int nrows)
{
    int w = (int)((blockIdx.x * blockDim.x + threadIdx.x) >> 5);
    int lane = threadIdx.x & 31;
    if (w >= nrows) return;
    int beg = rp[w], end = rp[w + 1];
    float4 acc = make_float4(0.f, 0.f, 0.f, 0.f);
    const float4* fv = (const float4*)feat;
    for (int e = beg; e < end; e++) {
        int s = __ldg(&col[e]);
        float4 v = __ldg(&fv[(size_t)s * 32 + lane]);
        acc.x += v.x; acc.y += v.y; acc.z += v.z; acc.w += v.w;
    }
    float inv = (end > beg) ? 1.f / (float)(end - beg) : 0.f;
    acc.x *= inv; acc.y *= inv; acc.z *= inv; acc.w *= inv;
    ((float4*)out)[(size_t)w * 32 + lane] = acc;
}

__global__ void k_wcomb(const float* __restrict__ W1r, const float* __restrict__ b1,
                        const float* __restrict__ W2r, const float* __restrict__ b2)
{
    int i = blockIdx.x * blockDim.x + threadIdx.x;
    float* Wc = g_f + OF_WC;
    float* bc = g_f + OF_BC;
    if (i < HH) {
        Wc[0*HH + i] = W1r[1*HH + i] + W1r[3*HH + i];
        Wc[1*HH + i] = W1r[2*HH + i] + W1r[4*HH + i];
        Wc[2*HH + i] = W2r[0*HH + i] + W2r[5*HH + i];
    }
    if (i < H) {
        bc[0*H + i] = b1[1*H + i] + b1[3*H + i];
        bc[1*H + i] = b1[2*H + i] + b1[4*H + i];
        bc[2*H + i] = b1[0*H + i] + b1[5*H + i];
        bc[3*H + i] = b2[0*H + i] + b2[5*H + i];
    }
}

// ======================= FFMA2 GEMM (layers) =================================
#define GEMM_ACC  1
#define GEMM_RELU 2

__global__ void __launch_bounds__(256)
k_gemm(const float* __restrict__ A0, const float* __restrict__ W0,
       const float* __restrict__ A1, const float* __restrict__ W1,
       const float* __restrict__ bias, float* __restrict__ C,
       int M, int N, int ldw, int flags)
{
    __shared__ float sA[16][128];
    __shared__ float sW[16][128];
    const int tid = threadIdx.x;
    const int tx = tid & 15;
    const int ty = tid >> 4;
    const int m0 = blockIdx.y * 128;
    const int n0 = blockIdx.x * 128;

    unsigned long long acc2[8][4];
#pragma unroll
    for (int i = 0; i < 8; i++)
#pragma unroll
        for (int j = 0; j < 4; j++) acc2[i][j] = 0ULL;

#pragma unroll 1
    for (int term = 0; term < 2; term++) {
        const float* A = term ? A1 : A0;
        const float* W = term ? W1 : W0;
        if (A == nullptr) break;
#pragma unroll 1
        for (int k0 = 0; k0 < H; k0 += 16) {
            {
                int l = tid;
#pragma unroll
                for (int r = 0; r < 2; r++, l += 256) {
                    int m = l >> 2;
                    int q = (l & 3) * 4;
                    float4 v = make_float4(0.f, 0.f, 0.f, 0.f);
                    if (m0 + m < M)
                        v = *(const float4*)(A + (size_t)(m0 + m) * H + k0 + q);
                    sA[q + 0][m] = v.x;
                    sA[q + 1][m] = v.y;
                    sA[q + 2][m] = v.z;
                    sA[q + 3][m] = v.w;
                }
            }
            {
                int l = tid;
#pragma unroll
                for (int r = 0; r < 2; r++, l += 256) {
                    int k  = l >> 5;
                    int nq = (l & 31) * 4;
                    float4 v = make_float4(0.f, 0.f, 0.f, 0.f);
                    if (n0 + nq < N)
                        v = *(const float4*)(W + (size_t)(k0 + k) * ldw + n0 + nq);
                    *(float4*)&sW[k][nq] = v;
                }
            }
            __syncthreads();
#pragma unroll
            for (int kk = 0; kk < 16; kk++) {
                float4 a0 = *(const float4*)&sA[kk][ty * 8];
                float4 a1 = *(const float4*)&sA[kk][ty * 8 + 4];
                ulonglong2 w0 = *(const ulonglong2*)&sW[kk][tx * 8];
                ulonglong2 w1 = *(const ulonglong2*)&sW[kk][tx * 8 + 4];
                unsigned long long B2[4] = { w0.x, w0.y, w1.x, w1.y };
                float ar[8] = { a0.x, a0.y, a0.z, a0.w, a1.x, a1.y, a1.z, a1.w };
                unsigned long long A2[8];
#pragma unroll
                for (int i = 0; i < 8; i++) {
                    unsigned int au = __float_as_uint(ar[i]);
                    asm("mov.b64 %0, {%1, %1};" : "=l"(A2[i]) : "r"(au));
                }
#pragma unroll
                for (int i = 0; i < 8; i++)
#pragma unroll
                    for (int j = 0; j < 4; j++)
                        asm("fma.rn.f32x2 %0, %1, %2, %0;"
                            : "+l"(acc2[i][j]) : "l"(A2[i]), "l"(B2[j]));
            }
            __syncthreads();
        }
    }

    const bool do_acc  = (flags & GEMM_ACC)  != 0;
    const bool do_relu = (flags & GEMM_RELU) != 0;
#pragma unroll
    for (int i = 0; i < 8; i++) {
        int m = m0 + ty * 8 + i;
        if (m >= M) continue;
        float vout[8];
#pragma unroll
        for (int j = 0; j < 4; j++) {
            union { unsigned long long u; float f[2]; } cv;
            cv.u = acc2[i][j];
            vout[2 * j + 0] = cv.f[0];
            vout[2 * j + 1] = cv.f[1];
        }
#pragma unroll
        for (int jq = 0; jq < 2; jq++) {
            int n = n0 + tx * 8 + jq * 4;
            if (n >= N) continue;
            float4 v = make_float4(vout[jq*4+0], vout[jq*4+1], vout[jq*4+2], vout[jq*4+3]);
            if (bias) {
                float4 b = *(const float4*)(bias + n);
                v.x += b.x; v.y += b.y; v.z += b.z; v.w += b.w;
            }
            float* cp = C + (size_t)m * N + n;
            if (do_acc) {
                float4 c = *(const float4*)cp;
                v.x += c.x; v.y += c.y; v.z += c.z; v.w += c.w;
            }
            if (do_relu) {
                v.x = fmaxf(v.x, 0.f); v.y = fmaxf(v.y, 0.f);
                v.z = fmaxf(v.z, 0.f); v.w = fmaxf(v.w, 0.f);
            }
            *(float4*)cp = v;
        }
    }
}

// ======================= bf16 split conversions ==============================
__global__ void k_splitA(const float* __restrict__ a,
                         __nv_bfloat16* __restrict__ hi, __nv_bfloat16* __restrict__ lo, int n)
{
    int t = blockIdx.x * blockDim.x + threadIdx.x;
    if (t >= n) return;
    float x = a[t];
    __nv_bfloat16 h = __float2bfloat16(x);
    hi[t] = h;
    lo[t] = __float2bfloat16(x - __bfloat162float(h));
}

// B: pred_W [H, NI] fp32 -> Bhi/Blo [NI, H] bf16 (transposed, K contiguous)
__global__ void __launch_bounds__(256)
k_splitB(const float* __restrict__ W,
         __nv_bfloat16* __restrict__ hi, __nv_bfloat16* __restrict__ lo)
{
    __shared__ float t[32][33];
    int nblk = blockIdx.x * 32;
    int kblk = blockIdx.y * 32;
    int tx = threadIdx.x, ty = threadIdx.y;   // block (32, 8)
#pragma unroll
    for (int i = ty; i < 32; i += 8)
        t[i][tx] = W[(size_t)(kblk + i) * NI + nblk + tx];
    __syncthreads();
#pragma unroll
    for (int i = ty; i < 32; i += 8) {
        float x = t[tx][i];
        __nv_bfloat16 h = __float2bfloat16(x);
        size_t o = (size_t)(nblk + i) * H + kblk + tx;
        hi[o] = h;
        lo[o] = __float2bfloat16(x - __bfloat162float(h));
    }
}

// ======================= HMMA prediction GEMM ================================
// out[NG, NI] = A[NG,128] @ Bt[NI,128]^T + bias, 3-split bf16, fp32 accum.
// 128x128 tile, 256 thr, 8 warps (4M x 2N), warp tile 32x64, K=128 resident.
#define PK   136              // padded row length in bf16 (conflict-free ldsm)
#define ROWB (PK * 2)         // 272 bytes per row
#define SA_HI 0
#define SA_LO (128 * ROWB)
#define SB_HI (2 * 128 * ROWB)
#define SB_LO (3 * 128 * ROWB)
#define SMEM_PRED (4 * 128 * ROWB)   // 139264 bytes

__global__ void __launch_bounds__(256, 1)
k_mma_pred(const __nv_bfloat16* __restrict__ Ahi, const __nv_bfloat16* __restrict__ Alo,
           const __nv_bfloat16* __restrict__ Bhi, const __nv_bfloat16* __restrict__ Blo,
           const float* __restrict__ bias, float* __restrict__ out)
{
    extern __shared__ char sm[];
    const int tid  = threadIdx.x;
    const int wid  = tid >> 5;
    const int lane = tid & 31;
    const int wm   = wid >> 1;           // 0..3
    const int wn   = wid & 1;            // 0..1
    const int m0   = blockIdx.y * 128;
    const int n0   = blockIdx.x * 128;

    // ---- global -> smem (all four split buffers, zero-fill at edges) ----
    const uint4* gAhi = (const uint4*)Ahi;
    const uint4* gAlo = (const uint4*)Alo;
    const uint4* gBhi = (const uint4*)Bhi;
    const uint4* gBlo = (const uint4*)Blo;
#pragma unroll 4
    for (int i = tid; i < 2048; i += 256) {     // 128 rows x 16 uint4
        int row = i >> 4, cq = i & 15;
        uint32_t soff = (uint32_t)row * ROWB + cq * 16;
        uint4 z = make_uint4(0, 0, 0, 0);
        uint4 vh = z, vl = z, wh = z, wl = z;
        if (m0 + row < NG) {
            size_t g = (size_t)(m0 + row) * 16 + cq;
            vh = __ldg(&gAhi[g]);
            vl = __ldg(&gAlo[g]);
        }
        if (n0 + row < NI) {
            size_t g = (size_t)(n0 + row) * 16 + cq;
            wh = __ldg(&gBhi[g]);
            wl = __ldg(&gBlo[g]);
        }
        *(uint4*)(sm + SA_HI + soff) = vh;
        *(uint4*)(sm + SA_LO + soff) = vl;
        *(uint4*)(sm + SB_HI + soff) = wh;
        *(uint4*)(sm + SB_LO + soff) = wl;
    }
    __syncthreads();

    const uint32_t sbase = smem_u32(sm);
    // ldmatrix lane addressing offsets
    const uint32_t a_loff = (uint32_t)(lane & 15) * ROWB + (uint32_t)(lane >> 4) * 16;
    const uint32_t b_loff = (uint32_t)(((lane >> 4) * 8) + (lane & 7)) * ROWB
                          + (uint32_t)((lane >> 3) & 1) * 16;

    float c[2][8][4];
#pragma unroll
    for (int i = 0; i < 2; i++)
#pragma unroll
        for (int j = 0; j < 8; j++)
#pragma unroll
            for (int q = 0; q < 4; q++) c[i][j][q] = 0.f;

#pragma unroll 1
    for (int term = 0; term < 3; term++) {
        uint32_t aB = sbase + (term == 2 ? SA_LO : SA_HI) + (uint32_t)wm * 32 * ROWB + a_loff;
        uint32_t bB = sbase + (term == 1 ? SB_LO : SB_HI) + (uint32_t)wn * 64 * ROWB + b_loff;
#pragma unroll
        for (int ks = 0; ks < 8; ks++) {
            uint32_t a[2][4], b[4][4];
            LDSM4(a[0], aB + ks * 32);
            LDSM4(a[1], aB + ks * 32 + 16 * ROWB);
#pragma unroll
            for (int g = 0; g < 4; g++)
                LDSM4(b[g], bB + ks * 32 + g * 16 * ROWB);
#pragma unroll
            for (int ma = 0; ma < 2; ma++)
#pragma unroll
                for (int na = 0; na < 8; na++)
                    MMA_BF16(c[ma][na], a[ma],
                             b[na >> 1][(na & 1) * 2], b[na >> 1][(na & 1) * 2 + 1]);
        }
    }

    // ---- epilogue: c frags + bias -> out ----
    const int gid = lane >> 2;
    const int tq  = (lane & 3) * 2;
#pragma unroll
    for (int ma = 0; ma < 2; ma++) {
#pragma unroll
        for (int na = 0; na < 8; na++) {
            int mrow = m0 + wm * 32 + ma * 16 + gid;
            int ncol = n0 + wn * 64 + na * 8 + tq;
            if (ncol >= NI) continue;
            float2 bv = *(const float2*)(bias + ncol);
            if (mrow < NG) {
                float2 v = make_float2(c[ma][na][0] + bv.x, c[ma][na][1] + bv.y);
                *(float2*)(out + (size_t)mrow * NI + ncol) = v;
            }
            if (mrow + 8 < NG) {
                float2 v = make_float2(c[ma][na][2] + bv.x, c[ma][na][3] + bv.y);
                *(float2*)(out + (size_t)(mrow + 8) * NI + ncol) = v;
            }
        }
    }
}

// ---------------------------------------------------------------------------
extern "C" void kernel_launch(void* const* d_in, const int* in_sizes, int n_in,
                              void* d_out, int out_size)
{
    const int*   x_user   = (const int*)  d_in[1];
    const int*   x_item   = (const int*)  d_in[2];
    const float* emb_user = (const float*)d_in[4];
    const float* emb_item = (const float*)d_in[5];
    const float* W1l      = (const float*)d_in[6];
    const float* W1r      = (const float*)d_in[7];
    const float* b1       = (const float*)d_in[8];
    const float* W2l      = (const float*)d_in[9];
    const float* W2r      = (const float*)d_in[10];
    const float* b2       = (const float*)d_in[11];
    const float* pred_W   = (const float*)d_in[12];
    const float* pred_b   = (const float*)d_in[13];
    const int*   ug_src   = (const int*)  d_in[14];
    const int*   ug_dst   = (const int*)  d_in[15];
    const int*   ui_src   = (const int*)  d_in[16];
    const int*   ui_dst   = (const int*)  d_in[17];
    const int*   gi_src   = (const int*)  d_in[18];
    const int*   gi_dst   = (const int*)  d_in[19];
    float* out = (float*)d_out;

    float* fb = nullptr; int* ib = nullptr; __nv_bfloat16* bb = nullptr;
    cudaGetSymbolAddress((void**)&fb, g_f);
    cudaGetSymbolAddress((void**)&ib, g_i);
    cudaGetSymbolAddress((void**)&bb, g_bf);

    cudaFuncSetAttribute(k_mma_pred, cudaFuncAttributeMaxDynamicSharedMemorySize,
                         SMEM_PRED);

    cudaMemsetAsync(ib + OI_CNT_G1, 0, (size_t)CNT_TOTAL * sizeof(int));

    // B split/transpose depends only on pred_W -> launch early
    {
        dim3 g(NI / 32, H / 32);
        k_splitB<<<g, dim3(32, 8)>>>(pred_W, bb + OB_BHI, bb + OB_BLO);
    }

    k_gather<<<(NU * 32 + 255) / 256, 256>>>(emb_user, x_user, fb + OF_HU, NU);
    k_gather<<<(NI * 32 + 255) / 256, 256>>>(emb_item, x_item, fb + OF_HI, NI);

    k_count<<<(E_UG + 255) / 256, 256>>>(ug_dst, E_UG, ib + OI_CNT_G1);
    k_count<<<(E_GI + 255) / 256, 256>>>(gi_src, E_GI, ib + OI_CNT_G2);
    k_count<<<(E_UI + 255) / 256, 256>>>(ui_src, E_UI, ib + OI_CNT_U);
    k_count<<<(E_UI + 255) / 256, 256>>>(ui_dst, E_UI, ib + OI_CNT_I);

    k_scan<<<1, 1024>>>(ib + OI_CNT_G1, ib + OI_RP_G1, ib + OI_CUR_G1, NG);
    k_scan<<<1, 1024>>>(ib + OI_CNT_G2, ib + OI_RP_G2, ib + OI_CUR_G2, NG);
    k_scan<<<1, 1024>>>(ib + OI_CNT_U,  ib + OI_RP_U,  ib + OI_CUR_U,  NU);
    k_scan<<<1, 1024>>>(ib + OI_CNT_I,  ib + OI_RP_I,  ib + OI_CUR_I,  NI);

    k_bucket<<<(E_UG + 255) / 256, 256>>>(ug_dst, ug_src, E_UG, ib + OI_CUR_G1, ib + OI_COL_G1);
    k_bucket<<<(E_GI + 255) / 256, 256>>>(gi_src, gi_dst, E_GI, ib + OI_CUR_G2, ib + OI_COL_G2);
    k_bucket<<<(E_UI + 255) / 256, 256>>>(ui_src, ui_dst, E_UI, ib + OI_CUR_U,  ib + OI_COL_U);
    k_bucket<<<(E_UI + 255) / 256, 256>>>(ui_dst, ui_src, E_UI, ib + OI_CUR_I,  ib + OI_COL_I);

    k_wcomb<<<(HH + 255) / 256, 256>>>(W1r, b1, W2r, b2);

    k_agg<<<(NU + 7) / 8, 256>>>(ib + OI_RP_U,  ib + OI_COL_U,  fb + OF_HI, fb + OF_AIU, NU);
    k_agg<<<(NI + 7) / 8, 256>>>(ib + OI_RP_I,  ib + OI_COL_I,  fb + OF_HU, fb + OF_AUI, NI);
    k_agg<<<(NG + 7) / 8, 256>>>(ib + OI_RP_G1, ib + OI_COL_G1, fb + OF_HU, fb + OF_AUG, NG);
    k_agg<<<(NG + 7) / 8, 256>>>(ib + OI_RP_G2, ib + OI_COL_G2, fb + OF_HI, fb + OF_AIG, NG);

    {
        dim3 g(1, (NU + 127) / 128);
        k_gemm<<<g, 256>>>(fb + OF_AIU, W1l + 3*HH, fb + OF_HU, fb + OF_WC + 0*HH,
                           fb + OF_BC + 0*H, fb + OF_HU1, NU, H, H, GEMM_RELU);
    }
    {
        dim3 g(1, (NI + 127) / 128);
        k_gemm<<<g, 256>>>(fb + OF_AUI, W1l + 2*HH, fb + OF_HI, fb + OF_WC + 1*HH,
                           fb + OF_BC + 1*H, fb + OF_HI1, NI, H, H, GEMM_RELU);
    }
    {
        dim3 g(1, (NG + 127) / 128);
        k_gemm<<<g, 256>>>(fb + OF_AUG, W1l + 0*HH, fb + OF_AIG, W1l + 5*HH,
                           fb + OF_BC + 2*H, fb + OF_HG1, NG, H, H, GEMM_RELU);
    }

    k_agg<<<(NG + 7) / 8, 256>>>(ib + OI_RP_G1, ib + OI_COL_G1, fb + OF_HU1, fb + OF_BUG, NG);
    k_agg<<<(NG + 7) / 8, 256>>>(ib + OI_RP_G2, ib + OI_COL_G2, fb + OF_HI1, fb + OF_BIG, NG);

    {
        dim3 g(1, (NG + 127) / 128);
        k_gemm<<<g, 256>>>(fb + OF_BUG, W2l + 0*HH, fb + OF_HG1, fb + OF_WC + 2*HH,
                           fb + OF_BC + 3*H, fb + OF_REP, NG, H, H, 0);
        k_gemm<<<g, 256>>>(fb + OF_BIG, W2l + 5*HH, nullptr, nullptr,
                           nullptr, fb + OF_REP, NG, H, H, GEMM_ACC | GEMM_RELU);
    }

    // bf16 split of rep, then tensor-pipe prediction GEMM
    k_splitA<<<(NG * H + 255) / 256, 256>>>(fb + OF_REP, bb + OB_AHI, bb + OB_ALO, NG * H);
    {
        dim3 g((NI + 127) / 128, (NG + 127) / 128);
        k_mma_pred<<<g, 256, SMEM_PRED>>>(bb + OB_AHI, bb + OB_ALO,
                                          bb + OB_BHI, bb + OB_BLO,
                                          pred_b, out);
    }
    (void)in_sizes; (void)n_in; (void)out_size;
}

// round 4
// speedup vs baseline: 1.3787x; 1.1000x over previous
#include <cuda_runtime.h>
#include <cuda_bf16.h>
#include <cstdint>

// ----------------------------------------------------------------------------
// BaseGR hetero-SAGE on GB300 — R4.
// All GEMMs on mma.sync bf16 (hi/lo 3-split, fp32 accum).
// Pred GEMM: persistent CTAs, A-resident, cp.async double-buffered B stream.
// Splits fused into producers (gather / seg-mean / GEMM epilogues).
// ----------------------------------------------------------------------------

#define NG 5000
#define NU 100000
#define NI 20000
#define H 128
#define HH (H*H)
#define E_UG 300000
#define E_UI 600000
#define E_GI 200000

// ---------------- fp32 scratch ----------------
#define OF_HU  0
#define OF_HI  (OF_HU  + NU*H)
#define OF_HU1 (OF_HI  + NI*H)
#define OF_HI1 (OF_HU1 + NU*H)
#define OF_WC  (OF_HI1 + NI*H)
#define OF_BC  (OF_WC  + 3*HH)
#define F_TOTAL (OF_BC + 4*H)
__device__ float g_f[F_TOTAL];

// ---------------- bf16 scratch (hi plane then lo plane for each) -------------
#define OB_HUe 0
#define OB_HIe (OB_HUe + 2*NU*H)
#define OB_AIU (OB_HIe + 2*NI*H)
#define OB_AUI (OB_AIU + 2*NU*H)
#define OB_AUG (OB_AUI + 2*NI*H)
#define OB_AIG (OB_AUG + 2*NG*H)
#define OB_HG1 (OB_AIG + 2*NG*H)
#define OB_BUG (OB_HG1 + 2*NG*H)
#define OB_BIG (OB_BUG + 2*NG*H)
#define OB_REP (OB_BIG + 2*NG*H)
#define OB_PW  (OB_REP + 2*NG*H)
#define OB_W   (OB_PW  + 2*NI*H)
#define B_TOTAL (OB_W + 18*HH)
__device__ __nv_bfloat16 g_bf[B_TOTAL];

// weight slots in OB_W (each slot: hi HH then lo HH)
#define SL_W1L3 0
#define SL_WC0  1
#define SL_W1L2 2
#define SL_WC1  3
#define SL_W1L0 4
#define SL_W1L5 5
#define SL_W2L0 6
#define SL_WC2  7
#define SL_W2L5 8

// ---------------- int scratch ----------------
#define OI_CNT_G1 0
#define OI_CNT_G2 (OI_CNT_G1 + NG)
#define OI_CNT_U  (OI_CNT_G2 + NG)
#define OI_CNT_I  (OI_CNT_U  + NU)
#define CNT_TOTAL (OI_CNT_I  + NI)
#define OI_RP_G1  CNT_TOTAL
#define OI_RP_G2  (OI_RP_G1 + NG + 1)
#define OI_RP_U   (OI_RP_G2 + NG + 1)
#define OI_RP_I   (OI_RP_U  + NU + 1)
#define OI_CUR_G1 (OI_RP_I  + NI + 1)
#define OI_CUR_G2 (OI_CUR_G1 + NG)
#define OI_CUR_U  (OI_CUR_G2 + NG)
#define OI_CUR_I  (OI_CUR_U  + NU)
#define OI_COL_G1 (OI_CUR_I  + NI)
#define OI_COL_G2 (OI_COL_G1 + E_UG)
#define OI_COL_U  (OI_COL_G2 + E_GI)
#define OI_COL_I  (OI_COL_U  + E_UI)
#define I_TOTAL   (OI_COL_I  + E_UI)
__device__ int g_i[I_TOTAL];

// ======================= helpers =============================================
__device__ __forceinline__ uint32_t smem_u32(const void* p) {
    uint32_t a;
    asm("{ .reg .u64 t; cvta.to.shared.u64 t, %1; cvt.u32.u64 %0, t; }"
        : "=r"(a) : "l"(p));
    return a;
}

#define LDSM4(r, addr) \
    asm volatile("ldmatrix.sync.aligned.m8n8.x4.shared.b16 {%0,%1,%2,%3}, [%4];" \
                 : "=r"((r)[0]), "=r"((r)[1]), "=r"((r)[2]), "=r"((r)[3]) \
                 : "r"(addr))

#define MMA_BF16(c, a, b0, b1) \
    asm volatile("mma.sync.aligned.m16n8k16.row.col.f32.bf16.bf16.f32 " \
                 "{%0,%1,%2,%3}, {%4,%5,%6,%7}, {%8,%9}, {%0,%1,%2,%3};" \
                 : "+f"((c)[0]), "+f"((c)[1]), "+f"((c)[2]), "+f"((c)[3]) \
                 : "r"((a)[0]), "r"((a)[1]), "r"((a)[2]), "r"((a)[3]), \
                   "r"(b0), "r"(b1))

#define CPA16(dst, src, sz) \
    asm volatile("cp.async.cg.shared.global [%0], [%1], 16, %2;" \
                 :: "r"(dst), "l"(src), "r"(sz))
#define CP_COMMIT() asm volatile("cp.async.commit_group;" ::: "memory")
#define CP_WAIT0()  asm volatile("cp.async.wait_group 0;" ::: "memory")
#define CP_WAIT1()  asm volatile("cp.async.wait_group 1;" ::: "memory")

// split v0,v1 into packed bf16 hi / lo words
__device__ __forceinline__ void bfsplit2(float v0, float v1, uint32_t& h, uint32_t& l)
{
    __nv_bfloat16 h0 = __float2bfloat16(v0), h1 = __float2bfloat16(v1);
    float r0 = v0 - __bfloat162float(h0);
    float r1 = v1 - __bfloat162float(h1);
    __nv_bfloat16 l0 = __float2bfloat16(r0), l1 = __float2bfloat16(r1);
    h = (uint32_t)__bfloat16_as_ushort(h0) | ((uint32_t)__bfloat16_as_ushort(h1) << 16);
    l = (uint32_t)__bfloat16_as_ushort(l0) | ((uint32_t)__bfloat16_as_ushort(l1) << 16);
}

// ======================= gather (fp32 + bf16 hi/lo) ==========================
__global__ void k_gather2(const float* __restrict__ emb, const int* __restrict__ x,
                          float* __restrict__ outf,
                          __nv_bfloat16* __restrict__ hb, int loOff, int n)
{
    int t = blockIdx.x * blockDim.x + threadIdx.x;
    if (t >= n * 32) return;
    int r = t >> 5, c = t & 31;
    float4 v = ((const float4*)emb)[(size_t)x[r] * 32 + c];
    ((float4*)outf)[t] = v;
    uint32_t h0, l0, h1, l1;
    bfsplit2(v.x, v.y, h0, l0);
    bfsplit2(v.z, v.w, h1, l1);
    size_t o = ((size_t)r * H + c * 4) >> 1;   // uint32 units (2 bf16)
    ((uint32_t*)hb)[o]     = h0;
    ((uint32_t*)hb)[o + 1] = h1;
    ((uint32_t*)(hb + loOff))[o]     = l0;
    ((uint32_t*)(hb + loOff))[o + 1] = l1;
}

// ======================= CSR build (merged) ==================================
__global__ void k_count_all(const int* __restrict__ ug_dst, const int* __restrict__ gi_src,
                            const int* __restrict__ ui_src, const int* __restrict__ ui_dst,
                            int* __restrict__ ib)
{
    int t = blockIdx.x * blockDim.x + threadIdx.x;
    if (t < E_UG) atomicAdd(&ib[OI_CNT_G1 + ug_dst[t]], 1);
    else if (t < E_UG + E_GI) atomicAdd(&ib[OI_CNT_G2 + gi_src[t - E_UG]], 1);
    else if (t < E_UG + E_GI + E_UI) atomicAdd(&ib[OI_CNT_U + ui_src[t - E_UG - E_GI]], 1);
    else if (t < E_UG + E_GI + 2*E_UI) atomicAdd(&ib[OI_CNT_I + ui_dst[t - E_UG - E_GI - E_UI]], 1);
}

__global__ void k_scan4(int* __restrict__ ib)
{
    const int* cnt; int* rp; int* cur; int n;
    switch (blockIdx.x) {
        case 0: cnt = ib + OI_CNT_G1; rp = ib + OI_RP_G1; cur = ib + OI_CUR_G1; n = NG; break;
        case 1: cnt = ib + OI_CNT_G2; rp = ib + OI_RP_G2; cur = ib + OI_CUR_G2; n = NG; break;
        case 2: cnt = ib + OI_CNT_U;  rp = ib + OI_RP_U;  cur = ib + OI_CUR_U;  n = NU; break;
        default: cnt = ib + OI_CNT_I; rp = ib + OI_RP_I;  cur = ib + OI_CUR_I;  n = NI; break;
    }
    __shared__ int ssum[1024];
    const int t = threadIdx.x;
    const int chunk = (n + 1023) / 1024;
    int beg = t * chunk;
    int end = beg + chunk; if (end > n) end = n;
    if (beg > n) beg = n;
    int s = 0;
    for (int i = beg; i < end; i++) s += cnt[i];
    ssum[t] = s;
    __syncthreads();
    for (int off = 1; off < 1024; off <<= 1) {
        int v = (t >= off) ? ssum[t - off] : 0;
        __syncthreads();
        ssum[t] += v;
        __syncthreads();
    }
    int prefix = (t == 0) ? 0 : ssum[t - 1];
    for (int i = beg; i < end; i++) {
        rp[i]  = prefix;
        cur[i] = prefix;
        prefix += cnt[i];
    }
    if (t == 1023) rp[n] = ssum[1023];
}

__global__ void k_bucket_all(const int* __restrict__ ug_src, const int* __restrict__ ug_dst,
                             const int* __restrict__ ui_src, const int* __restrict__ ui_dst,
                             const int* __restrict__ gi_src, const int* __restrict__ gi_dst,
                             int* __restrict__ ib)
{
    int t = blockIdx.x * blockDim.x + threadIdx.x;
    if (t < E_UG) {
        int p = atomicAdd(&ib[OI_CUR_G1 + ug_dst[t]], 1);
        ib[OI_COL_G1 + p] = ug_src[t];
    } else if (t < E_UG + E_GI) {
        int e = t - E_UG;
        int p = atomicAdd(&ib[OI_CUR_G2 + gi_src[e]], 1);
        ib[OI_COL_G2 + p] = gi_dst[e];
    } else if (t < E_UG + E_GI + E_UI) {
        int e = t - E_UG - E_GI;
        int p = atomicAdd(&ib[OI_CUR_U + ui_src[e]], 1);
        ib[OI_COL_U + p] = ui_dst[e];
    } else if (t < E_UG + E_GI + 2*E_UI) {
        int e = t - E_UG - E_GI - E_UI;
        int p = atomicAdd(&ib[OI_CUR_I + ui_dst[e]], 1);
        ib[OI_COL_I + p] = ui_src[e];
    }
}

// ======================= segment mean -> bf16 hi/lo ==========================
__device__ __forceinline__ void agg_row(const int* __restrict__ rp, const int* __restrict__ col,
                                        const float* __restrict__ feat,
                                        __nv_bfloat16* __restrict__ hb, int loOff,
                                        int row, int lane)
{
    int beg = rp[row], end = rp[row + 1];
    float4 acc = make_float4(0.f, 0.f, 0.f, 0.f);
    const float4* fv = (const float4*)feat;
    for (int e = beg; e < end; e++) {
        int s = __ldg(&col[e]);
        float4 v = __ldg(&fv[(size_t)s * 32 + lane]);
        acc.x += v.x; acc.y += v.y; acc.z += v.z; acc.w += v.w;
    }
    float inv = (end > beg) ? 1.f / (float)(end - beg) : 0.f;
    acc.x *= inv; acc.y *= inv; acc.z *= inv; acc.w *= inv;
    uint32_t h0, l0, h1, l1;
    bfsplit2(acc.x, acc.y, h0, l0);
    bfsplit2(acc.z, acc.w, h1, l1);
    size_t o = ((size_t)row * H + lane * 4) >> 1;
    ((uint32_t*)hb)[o]     = h0;
    ((uint32_t*)hb)[o + 1] = h1;
    ((uint32_t*)(hb + loOff))[o]     = l0;
    ((uint32_t*)(hb + loOff))[o + 1] = l1;
}

// layer-1 aggregations: AIU (items->users), AUI (users->items), AUG, AIG
__global__ void k_agg_all(const int* __restrict__ ib, const float* __restrict__ fb,
                          __nv_bfloat16* __restrict__ bb)
{
    int w = (int)((blockIdx.x * blockDim.x + threadIdx.x) >> 5);
    int lane = threadIdx.x & 31;
    if (w < NU)
        agg_row(ib + OI_RP_U, ib + OI_COL_U, fb + OF_HI, bb + OB_AIU, NU*H, w, lane);
    else if (w < NU + NI)
        agg_row(ib + OI_RP_I, ib + OI_COL_I, fb + OF_HU, bb + OB_AUI, NI*H, w - NU, lane);
    else if (w < NU + NI + NG)
        agg_row(ib + OI_RP_G1, ib + OI_COL_G1, fb + OF_HU, bb + OB_AUG, NG*H, w - NU - NI, lane);
    else if (w < NU + NI + 2*NG)
        agg_row(ib + OI_RP_G2, ib + OI_COL_G2, fb + OF_HI, bb + OB_AIG, NG*H, w - NU - NI - NG, lane);
}

// layer-2 aggregations: BUG (users->groups of HU1), BIG (items->groups of HI1)
__global__ void k_agg_all2(const int* __restrict__ ib, const float* __restrict__ fb,
                           __nv_bfloat16* __restrict__ bb)
{
    int w = (int)((blockIdx.x * blockDim.x + threadIdx.x) >> 5);
    int lane = threadIdx.x & 31;
    if (w < NG)
        agg_row(ib + OI_RP_G1, ib + OI_COL_G1, fb + OF_HU1, bb + OB_BUG, NG*H, w, lane);
    else if (w < 2*NG)
        agg_row(ib + OI_RP_G2, ib + OI_COL_G2, fb + OF_HI1, bb + OB_BIG, NG*H, w - NG, lane);
}

// ======================= weight prep =========================================
__global__ void k_wcomb(const float* __restrict__ W1r, const float* __restrict__ b1,
                        const float* __restrict__ W2r, const float* __restrict__ b2)
{
    int i = blockIdx.x * blockDim.x + threadIdx.x;
    float* Wc = g_f + OF_WC;
    float* bc = g_f + OF_BC;
    if (i < HH) {
        Wc[0*HH + i] = W1r[1*HH + i] + W1r[3*HH + i];
        Wc[1*HH + i] = W1r[2*HH + i] + W1r[4*HH + i];
        Wc[2*HH + i] = W2r[0*HH + i] + W2r[5*HH + i];
    }
    if (i < H) {
        bc[0*H + i] = b1[1*H + i] + b1[3*H + i];
        bc[1*H + i] = b1[2*H + i] + b1[4*H + i];
        bc[2*H + i] = b1[0*H + i] + b1[5*H + i];
        bc[3*H + i] = b2[0*H + i] + b2[5*H + i];
    }
}

// transpose+split 9 HxH weights into Bt [n][k] hi/lo bf16
__global__ void __launch_bounds__(256)
k_splitW(const float* __restrict__ W1l, const float* __restrict__ W2l,
         const float* __restrict__ Wc, __nv_bfloat16* __restrict__ dst9)
{
    const float* src;
    switch (blockIdx.z) {
        case 0: src = W1l + 3*HH; break;
        case 1: src = Wc  + 0*HH; break;
        case 2: src = W1l + 2*HH; break;
        case 3: src = Wc  + 1*HH; break;
        case 4: src = W1l + 0*HH; break;
        case 5: src = W1l + 5*HH; break;
        case 6: src = W2l + 0*HH; break;
        case 7: src = Wc  + 2*HH; break;
        default: src = W2l + 5*HH; break;
    }
    __nv_bfloat16* hi = dst9 + (size_t)blockIdx.z * 2 * HH;
    __nv_bfloat16* lo = hi + HH;
    __shared__ float t[32][33];
    int nblk = blockIdx.x * 32;
    int kblk = blockIdx.y * 32;
    int tx = threadIdx.x, ty = threadIdx.y;
#pragma unroll
    for (int i = ty; i < 32; i += 8)
        t[i][tx] = src[(size_t)(kblk + i) * H + nblk + tx];
    __syncthreads();
#pragma unroll
    for (int i = ty; i < 32; i += 8) {
        float x = t[tx][i];
        __nv_bfloat16 h = __float2bfloat16(x);
        size_t o = (size_t)(nblk + i) * H + kblk + tx;
        hi[o] = h;
        lo[o] = __float2bfloat16(x - __bfloat162float(h));
    }
}

// pred_W [H, NI] fp32 -> [NI, H] bf16 hi/lo (transposed, K contiguous)
__global__ void __launch_bounds__(256)
k_splitB(const float* __restrict__ W,
         __nv_bfloat16* __restrict__ hi, __nv_bfloat16* __restrict__ lo)
{
    __shared__ float t[32][33];
    int nblk = blockIdx.x * 32;
    int kblk = blockIdx.y * 32;
    int tx = threadIdx.x, ty = threadIdx.y;
#pragma unroll
    for (int i = ty; i < 32; i += 8)
        t[i][tx] = W[(size_t)(kblk + i) * NI + nblk + tx];
    __syncthreads();
#pragma unroll
    for (int i = ty; i < 32; i += 8) {
        float x = t[tx][i];
        __nv_bfloat16 h = __float2bfloat16(x);
        size_t o = (size_t)(nblk + i) * H + kblk + tx;
        hi[o] = h;
        lo[o] = __float2bfloat16(x - __bfloat162float(h));
    }
}

// ======================= HMMA layer GEMM (multi-term) ========================
// C[M,128] = act( sum_t A_t[M,128] @ W_t[128,128]^T + bias )
// Tile 128x128, 256 thr, warp tile 32x64; bf16 3-split per term.
#define PK   136
#define ROWB (PK * 2)          // 272 B per row
#define TILEB (128 * ROWB)     // 34816 B

#define GEMM_RELU 1
#define GEMM_BF16 2

struct GemmArgs {
    const __nv_bfloat16* Ah[3];   // A hi plane
    const __nv_bfloat16* Al[3];   // A lo plane
    const __nv_bfloat16* Wh[3];   // W hi (lo at +HH)
    const float* bias;
    float* Cf;
    __nv_bfloat16* Cb;
    int M, nterms, flags, loOff;
};

#define SMEM_GH (4 * TILEB)    // 139264

__global__ void __launch_bounds__(256, 1)
k_gemm_h(GemmArgs g)
{
    extern __shared__ char sm[];
    const int tid  = threadIdx.x;
    const int wid  = tid >> 5;
    const int lane = tid & 31;
    const int wm   = wid >> 1;
    const int wn   = wid & 1;
    const int m0   = blockIdx.x * 128;

    const uint32_t sbase  = smem_u32(sm);
    const uint32_t a_loff = (uint32_t)(lane & 15) * ROWB + (uint32_t)(lane >> 4) * 16;
    const uint32_t b_loff = (uint32_t)(((lane >> 4) * 8) + (lane & 7)) * ROWB
                          + (uint32_t)((lane >> 3) & 1) * 16;

    float c[2][8][4];
#pragma unroll
    for (int i = 0; i < 2; i++)
#pragma unroll
        for (int j = 0; j < 8; j++)
#pragma unroll
            for (int q = 0; q < 4; q++) c[i][j][q] = 0.f;

#pragma unroll 1
    for (int t = 0; t < g.nterms; t++) {
        const uint4* wh = (const uint4*)g.Wh[t];
        const uint4* wl = (const uint4*)(g.Wh[t] + HH);
        const uint4* ah = (const uint4*)g.Ah[t];
        const uint4* al = (const uint4*)g.Al[t];
#pragma unroll 4
        for (int i = tid; i < 2048; i += 256) {
            int row = i >> 4, cq = i & 15;
            uint32_t so = (uint32_t)row * ROWB + cq * 16;
            *(uint4*)(sm + 0*TILEB + so) = __ldg(&wh[row * 16 + cq]);
            *(uint4*)(sm + 1*TILEB + so) = __ldg(&wl[row * 16 + cq]);
            uint4 va = make_uint4(0,0,0,0), vb = va;
            if (m0 + row < g.M) {
                size_t gi = (size_t)(m0 + row) * 16 + cq;
                va = __ldg(&ah[gi]);
                vb = __ldg(&al[gi]);
            }
            *(uint4*)(sm + 2*TILEB + so) = va;
            *(uint4*)(sm + 3*TILEB + so) = vb;
        }
        __syncthreads();
#pragma unroll 1
        for (int sp = 0; sp < 3; sp++) {
            uint32_t aB = sbase + (sp == 2 ? 3*TILEB : 2*TILEB)
                        + (uint32_t)wm * 32 * ROWB + a_loff;
            uint32_t bB = sbase + (sp == 1 ? 1*TILEB : 0)
                        + (uint32_t)wn * 64 * ROWB + b_loff;
#pragma unroll
            for (int ks = 0; ks < 8; ks++) {
                uint32_t a[2][4], b[4][4];
                LDSM4(a[0], aB + ks * 32);
                LDSM4(a[1], aB + ks * 32 + 16 * ROWB);
#pragma unroll
                for (int q = 0; q < 4; q++)
                    LDSM4(b[q], bB + ks * 32 + q * 16 * ROWB);
#pragma unroll
                for (int ma = 0; ma < 2; ma++)
#pragma unroll
                    for (int na = 0; na < 8; na++)
                        MMA_BF16(c[ma][na], a[ma],
                                 b[na >> 1][(na & 1) * 2], b[na >> 1][(na & 1) * 2 + 1]);
            }
        }
        __syncthreads();
    }

    const int gid = lane >> 2;
    const int tq  = (lane & 3) * 2;
    const bool relu = (g.flags & GEMM_RELU) != 0;
    const bool bfo  = (g.flags & GEMM_BF16) != 0;
#pragma unroll
    for (int ma = 0; ma < 2; ma++) {
#pragma unroll
        for (int na = 0; na < 8; na++) {
            int mrow = m0 + wm * 32 + ma * 16 + gid;
            int ncol = wn * 64 + na * 8 + tq;
            float2 bv = *(const float2*)(g.bias + ncol);
#pragma unroll
            for (int hrow = 0; hrow < 2; hrow++) {
                int mr = mrow + hrow * 8;
                if (mr >= g.M) continue;
                float v0 = c[ma][na][hrow*2 + 0] + bv.x;
                float v1 = c[ma][na][hrow*2 + 1] + bv.y;
                if (relu) { v0 = fmaxf(v0, 0.f); v1 = fmaxf(v1, 0.f); }
                if (bfo) {
                    uint32_t hw, lw;
                    bfsplit2(v0, v1, hw, lw);
                    *(uint32_t*)(g.Cb + (size_t)mr * H + ncol) = hw;
                    *(uint32_t*)(g.Cb + (size_t)g.loOff + (size_t)mr * H + ncol) = lw;
                } else {
                    *(float2*)(g.Cf + (size_t)mr * H + ncol) = make_float2(v0, v1);
                }
            }
        }
    }
}

// ======================= pipelined pred GEMM =================================
// out[NG, NI] = REP[NG,128] @ PW[NI,128]^T + bias.
// A resident per CTA; B tiles streamed via cp.async double buffer.
#define NT_PRED ((NI + 127) / 128)   // 157
#define NSPLIT 8
#define SMEM_PRED (6 * TILEB)        // 208896

__global__ void __launch_bounds__(256, 1)
k_mma_pred(const __nv_bfloat16* __restrict__ Ahi, const __nv_bfloat16* __restrict__ Alo,
           const __nv_bfloat16* __restrict__ Bhi, const __nv_bfloat16* __restrict__ Blo,
           const float* __restrict__ bias, float* __restrict__ out)
{
    extern __shared__ char sm[];
    const int tid  = threadIdx.x;
    const int wid  = tid >> 5;
    const int lane = tid & 31;
    const int wm   = wid >> 1;
    const int wn   = wid & 1;
    const int m0   = blockIdx.y * 128;

    const uint32_t sbase = smem_u32(sm);
    const uint32_t sB    = sbase + 2 * TILEB;   // B region (2 bufs x hi/lo)

    // A tiles (hi/lo) via cp.async
    {
        const uint4* gh = (const uint4*)Ahi;
        const uint4* gl = (const uint4*)Alo;
#pragma unroll 4
        for (int i = tid; i < 2048; i += 256) {
            int row = i >> 4, cq = i & 15;
            int gr = m0 + row;
            int sz = (gr < NG) ? 16 : 0;
            if (gr >= NG) gr = NG - 1;
            uint32_t so = sbase + (uint32_t)row * ROWB + cq * 16;
            CPA16(so,         gh + (size_t)gr * 16 + cq, sz);
            CPA16(so + TILEB, gl + (size_t)gr * 16 + cq, sz);
        }
    }
    // first B tile
    {
        int n0_ = blockIdx.x * 128;
        const uint4* gh = (const uint4*)Bhi;
        const uint4* gl = (const uint4*)Blo;
#pragma unroll 4
        for (int i = tid; i < 2048; i += 256) {
            int row = i >> 4, cq = i & 15;
            int gr = n0_ + row;
            int sz = (gr < NI) ? 16 : 0;
            if (gr >= NI) gr = NI - 1;
            uint32_t so = sB + (uint32_t)row * ROWB + cq * 16;
            CPA16(so,         gh + (size_t)gr * 16 + cq, sz);
            CPA16(so + TILEB, gl + (size_t)gr * 16 + cq, sz);
        }
    }
    CP_COMMIT();

    const uint32_t a_loff = (uint32_t)(lane & 15) * ROWB + (uint32_t)(lane >> 4) * 16;
    const uint32_t b_loff = (uint32_t)(((lane >> 4) * 8) + (lane & 7)) * ROWB
                          + (uint32_t)((lane >> 3) & 1) * 16;
    const int gid = lane >> 2;
    const int tq  = (lane & 3) * 2;

    int buf = 0;
#pragma unroll 1
    for (int t = blockIdx.x; t < NT_PRED; t += NSPLIT) {
        int tn = t + NSPLIT;
        if (tn < NT_PRED) {
            // prefetch next B tile into other buffer
            int n0_ = tn * 128;
            const uint4* gh = (const uint4*)Bhi;
            const uint4* gl = (const uint4*)Blo;
            uint32_t dstB = sB + (uint32_t)(buf ^ 1) * (2 * TILEB);
#pragma unroll 4
            for (int i = tid; i < 2048; i += 256) {
                int row = i >> 4, cq = i & 15;
                int gr = n0_ + row;
                int sz = (gr < NI) ? 16 : 0;
                if (gr >= NI) gr = NI - 1;
                uint32_t so = dstB + (uint32_t)row * ROWB + cq * 16;
                CPA16(so,         gh + (size_t)gr * 16 + cq, sz);
                CPA16(so + TILEB, gl + (size_t)gr * 16 + cq, sz);
            }
            CP_COMMIT();
            CP_WAIT1();
        } else {
            CP_WAIT0();
        }
        __syncthreads();

        float c[2][8][4];
#pragma unroll
        for (int i = 0; i < 2; i++)
#pragma unroll
            for (int j = 0; j < 8; j++)
#pragma unroll
                for (int q = 0; q < 4; q++) c[i][j][q] = 0.f;

        uint32_t curB = sB + (uint32_t)buf * (2 * TILEB);
#pragma unroll 1
        for (int sp = 0; sp < 3; sp++) {
            uint32_t aB = sbase + (sp == 2 ? TILEB : 0) + (uint32_t)wm * 32 * ROWB + a_loff;
            uint32_t bB = curB + (sp == 1 ? TILEB : 0) + (uint32_t)wn * 64 * ROWB + b_loff;
#pragma unroll
            for (int ks = 0; ks < 8; ks++) {
                uint32_t a[2][4], b[4][4];
                LDSM4(a[0], aB + ks * 32);
                LDSM4(a[1], aB + ks * 32 + 16 * ROWB);
#pragma unroll
                for (int q = 0; q < 4; q++)
                    LDSM4(b[q], bB + ks * 32 + q * 16 * ROWB);
#pragma unroll
                for (int ma = 0; ma < 2; ma++)
#pragma unroll
                    for (int na = 0; na < 8; na++)
                        MMA_BF16(c[ma][na], a[ma],
                                 b[na >> 1][(na & 1) * 2], b[na >> 1][(na & 1) * 2 + 1]);
            }
        }

        // epilogue for tile t
        int n0_ = t * 128;
#pragma unroll
        for (int ma = 0; ma < 2; ma++) {
#pragma unroll
            for (int na = 0; na < 8; na++) {
                int mrow = m0 + wm * 32 + ma * 16 + gid;
                int ncol = n0_ + wn * 64 + na * 8 + tq;
                if (ncol >= NI) continue;
                float2 bv = *(const float2*)(bias + ncol);
                if (mrow < NG) {
                    float2 v = make_float2(c[ma][na][0] + bv.x, c[ma][na][1] + bv.y);
                    *(float2*)(out + (size_t)mrow * NI + ncol) = v;
                }
                if (mrow + 8 < NG) {
                    float2 v = make_float2(c[ma][na][2] + bv.x, c[ma][na][3] + bv.y);
                    *(float2*)(out + (size_t)(mrow + 8) * NI + ncol) = v;
                }
            }
        }
        __syncthreads();
        buf ^= 1;
    }
}

// ---------------------------------------------------------------------------
extern "C" void kernel_launch(void* const* d_in, const int* in_sizes, int n_in,
                              void* d_out, int out_size)
{
    const int*   x_user   = (const int*)  d_in[1];
    const int*   x_item   = (const int*)  d_in[2];
    const float* emb_user = (const float*)d_in[4];
    const float* emb_item = (const float*)d_in[5];
    const float* W1l      = (const float*)d_in[6];
    const float* W1r      = (const float*)d_in[7];
    const float* b1       = (const float*)d_in[8];
    const float* W2l      = (const float*)d_in[9];
    const float* W2r      = (const float*)d_in[10];
    const float* b2       = (const float*)d_in[11];
    const float* pred_W   = (const float*)d_in[12];
    const float* pred_b   = (const float*)d_in[13];
    const int*   ug_src   = (const int*)  d_in[14];
    const int*   ug_dst   = (const int*)  d_in[15];
    const int*   ui_src   = (const int*)  d_in[16];
    const int*   ui_dst   = (const int*)  d_in[17];
    const int*   gi_src   = (const int*)  d_in[18];
    const int*   gi_dst   = (const int*)  d_in[19];
    float* out = (float*)d_out;

    float* fb = nullptr; int* ib = nullptr; __nv_bfloat16* bb = nullptr;
    cudaGetSymbolAddress((void**)&fb, g_f);
    cudaGetSymbolAddress((void**)&ib, g_i);
    cudaGetSymbolAddress((void**)&bb, g_bf);

    cudaFuncSetAttribute(k_gemm_h, cudaFuncAttributeMaxDynamicSharedMemorySize, SMEM_GH);
    cudaFuncSetAttribute(k_mma_pred, cudaFuncAttributeMaxDynamicSharedMemorySize, SMEM_PRED);

    cudaMemsetAsync(ib + OI_CNT_G1, 0, (size_t)CNT_TOTAL * sizeof(int));

    // weight prep
    k_splitB<<<dim3(NI / 32, H / 32), dim3(32, 8)>>>(pred_W, bb + OB_PW, bb + OB_PW + NI*H);
    k_wcomb<<<(HH + 255) / 256, 256>>>(W1r, b1, W2r, b2);
    k_splitW<<<dim3(4, 4, 9), dim3(32, 8)>>>(W1l, W2l, fb + OF_WC, bb + OB_W);

    // embedding gathers (fp32 + bf16 hi/lo)
    k_gather2<<<(NU * 32 + 255) / 256, 256>>>(emb_user, x_user, fb + OF_HU,
                                              bb + OB_HUe, NU*H, NU);
    k_gather2<<<(NI * 32 + 255) / 256, 256>>>(emb_item, x_item, fb + OF_HI,
                                              bb + OB_HIe, NI*H, NI);

    // CSR build
    {
        int tot = E_UG + E_GI + 2 * E_UI;
        k_count_all<<<(tot + 255) / 256, 256>>>(ug_dst, gi_src, ui_src, ui_dst, ib);
        k_scan4<<<4, 1024>>>(ib);
        k_bucket_all<<<(tot + 255) / 256, 256>>>(ug_src, ug_dst, ui_src, ui_dst,
                                                 gi_src, gi_dst, ib);
    }

    // layer-1 aggregations -> bf16 hi/lo
    {
        int warps = NU + NI + 2 * NG;
        k_agg_all<<<(warps + 7) / 8, 256>>>(ib, fb, bb);
    }

    // layer-1 GEMMs
    {
        GemmArgs a = {};
        a.Ah[0] = bb + OB_AIU;  a.Al[0] = bb + OB_AIU + NU*H;  a.Wh[0] = bb + OB_W + SL_W1L3*2*HH;
        a.Ah[1] = bb + OB_HUe;  a.Al[1] = bb + OB_HUe + NU*H;  a.Wh[1] = bb + OB_W + SL_WC0*2*HH;
        a.bias = fb + OF_BC + 0*H;
        a.Cf = fb + OF_HU1; a.M = NU; a.nterms = 2; a.flags = GEMM_RELU;
        k_gemm_h<<<(NU + 127) / 128, 256, SMEM_GH>>>(a);
    }
    {
        GemmArgs a = {};
        a.Ah[0] = bb + OB_AUI;  a.Al[0] = bb + OB_AUI + NI*H;  a.Wh[0] = bb + OB_W + SL_W1L2*2*HH;
        a.Ah[1] = bb + OB_HIe;  a.Al[1] = bb + OB_HIe + NI*H;  a.Wh[1] = bb + OB_W + SL_WC1*2*HH;
        a.bias = fb + OF_BC + 1*H;
        a.Cf = fb + OF_HI1; a.M = NI; a.nterms = 2; a.flags = GEMM_RELU;
        k_gemm_h<<<(NI + 127) / 128, 256, SMEM_GH>>>(a);
    }
    {
        GemmArgs a = {};
        a.Ah[0] = bb + OB_AUG;  a.Al[0] = bb + OB_AUG + NG*H;  a.Wh[0] = bb + OB_W + SL_W1L0*2*HH;
        a.Ah[1] = bb + OB_AIG;  a.Al[1] = bb + OB_AIG + NG*H;  a.Wh[1] = bb + OB_W + SL_W1L5*2*HH;
        a.bias = fb + OF_BC + 2*H;
        a.Cb = bb + OB_HG1; a.loOff = NG*H;
        a.M = NG; a.nterms = 2; a.flags = GEMM_RELU | GEMM_BF16;
        k_gemm_h<<<(NG + 127) / 128, 256, SMEM_GH>>>(a);
    }

    // layer-2 aggregations
    k_agg_all2<<<(2 * NG + 7) / 8, 256>>>(ib, fb, bb);

    // layer-2 group GEMM (3 terms) -> REP bf16 hi/lo
    {
        GemmArgs a = {};
        a.Ah[0] = bb + OB_BUG;  a.Al[0] = bb + OB_BUG + NG*H;  a.Wh[0] = bb + OB_W + SL_W2L0*2*HH;
        a.Ah[1] = bb + OB_HG1;  a.Al[1] = bb + OB_HG1 + NG*H;  a.Wh[1] = bb + OB_W + SL_WC2*2*HH;
        a.Ah[2] = bb + OB_BIG;  a.Al[2] = bb + OB_BIG + NG*H;  a.Wh[2] = bb + OB_W + SL_W2L5*2*HH;
        a.bias = fb + OF_BC + 3*H;
        a.Cb = bb + OB_REP; a.loOff = NG*H;
        a.M = NG; a.nterms = 3; a.flags = GEMM_RELU | GEMM_BF16;
        k_gemm_h<<<(NG + 127) / 128, 256, SMEM_GH>>>(a);
    }

    // prediction GEMM
    {
        dim3 g(NSPLIT, (NG + 127) / 128);
        k_mma_pred<<<g, 256, SMEM_PRED>>>(bb + OB_REP, bb + OB_REP + NG*H,
                                          bb + OB_PW,  bb + OB_PW + NI*H,
                                          pred_b, out);
    }
    (void)in_sizes; (void)n_in; (void)out_size;
}

// round 5
// speedup vs baseline: 1.5662x; 1.1360x over previous
#include <cuda_runtime.h>
#include <cuda_bf16.h>
#include <cstdint>

// ----------------------------------------------------------------------------
// BaseGR hetero-SAGE on GB300 — R5.
// vs R4: (1) pred GEMM is persistent (148 CTAs, contiguous tile chunks,
// cp.async double-buffered B, A reloaded on m-row change) to kill wave
// quantization; (2) aggregation edge loop unrolled 4-wide for MLP.
// ----------------------------------------------------------------------------

#define NG 5000
#define NU 100000
#define NI 20000
#define H 128
#define HH (H*H)
#define E_UG 300000
#define E_UI 600000
#define E_GI 200000

// ---------------- fp32 scratch ----------------
#define OF_HU  0
#define OF_HI  (OF_HU  + NU*H)
#define OF_HU1 (OF_HI  + NI*H)
#define OF_HI1 (OF_HU1 + NU*H)
#define OF_WC  (OF_HI1 + NI*H)
#define OF_BC  (OF_WC  + 3*HH)
#define F_TOTAL (OF_BC + 4*H)
__device__ float g_f[F_TOTAL];

// ---------------- bf16 scratch (hi plane then lo plane for each) -------------
#define OB_HUe 0
#define OB_HIe (OB_HUe + 2*NU*H)
#define OB_AIU (OB_HIe + 2*NI*H)
#define OB_AUI (OB_AIU + 2*NU*H)
#define OB_AUG (OB_AUI + 2*NI*H)
#define OB_AIG (OB_AUG + 2*NG*H)
#define OB_HG1 (OB_AIG + 2*NG*H)
#define OB_BUG (OB_HG1 + 2*NG*H)
#define OB_BIG (OB_BUG + 2*NG*H)
#define OB_REP (OB_BIG + 2*NG*H)
#define OB_PW  (OB_REP + 2*NG*H)
#define OB_W   (OB_PW  + 2*NI*H)
#define B_TOTAL (OB_W + 18*HH)
__device__ __nv_bfloat16 g_bf[B_TOTAL];

// weight slots in OB_W (each slot: hi HH then lo HH)
#define SL_W1L3 0
#define SL_WC0  1
#define SL_W1L2 2
#define SL_WC1  3
#define SL_W1L0 4
#define SL_W1L5 5
#define SL_W2L0 6
#define SL_WC2  7
#define SL_W2L5 8

// ---------------- int scratch ----------------
#define OI_CNT_G1 0
#define OI_CNT_G2 (OI_CNT_G1 + NG)
#define OI_CNT_U  (OI_CNT_G2 + NG)
#define OI_CNT_I  (OI_CNT_U  + NU)
#define CNT_TOTAL (OI_CNT_I  + NI)
#define OI_RP_G1  CNT_TOTAL
#define OI_RP_G2  (OI_RP_G1 + NG + 1)
#define OI_RP_U   (OI_RP_G2 + NG + 1)
#define OI_RP_I   (OI_RP_U  + NU + 1)
#define OI_CUR_G1 (OI_RP_I  + NI + 1)
#define OI_CUR_G2 (OI_CUR_G1 + NG)
#define OI_CUR_U  (OI_CUR_G2 + NG)
#define OI_CUR_I  (OI_CUR_U  + NU)
#define OI_COL_G1 (OI_CUR_I  + NI)
#define OI_COL_G2 (OI_COL_G1 + E_UG)
#define OI_COL_U  (OI_COL_G2 + E_GI)
#define OI_COL_I  (OI_COL_U  + E_UI)
#define I_TOTAL   (OI_COL_I  + E_UI)
__device__ int g_i[I_TOTAL];

// ======================= helpers =============================================
__device__ __forceinline__ uint32_t smem_u32(const void* p) {
    uint32_t a;
    asm("{ .reg .u64 t; cvta.to.shared.u64 t, %1; cvt.u32.u64 %0, t; }"
        : "=r"(a) : "l"(p));
    return a;
}

#define LDSM4(r, addr) \
    asm volatile("ldmatrix.sync.aligned.m8n8.x4.shared.b16 {%0,%1,%2,%3}, [%4];" \
                 : "=r"((r)[0]), "=r"((r)[1]), "=r"((r)[2]), "=r"((r)[3]) \
                 : "r"(addr))

#define MMA_BF16(c, a, b0, b1) \
    asm volatile("mma.sync.aligned.m16n8k16.row.col.f32.bf16.bf16.f32 " \
                 "{%0,%1,%2,%3}, {%4,%5,%6,%7}, {%8,%9}, {%0,%1,%2,%3};" \
                 : "+f"((c)[0]), "+f"((c)[1]), "+f"((c)[2]), "+f"((c)[3]) \
                 : "r"((a)[0]), "r"((a)[1]), "r"((a)[2]), "r"((a)[3]), \
                   "r"(b0), "r"(b1))

#define CPA16(dst, src, sz) \
    asm volatile("cp.async.cg.shared.global [%0], [%1], 16, %2;" \
                 :: "r"(dst), "l"(src), "r"(sz))
#define CP_COMMIT() asm volatile("cp.async.commit_group;" ::: "memory")
#define CP_WAIT0()  asm volatile("cp.async.wait_group 0;" ::: "memory")
#define CP_WAIT1()  asm volatile("cp.async.wait_group 1;" ::: "memory")

// split v0,v1 into packed bf16 hi / lo words
__device__ __forceinline__ void bfsplit2(float v0, float v1, uint32_t& h, uint32_t& l)
{
    __nv_bfloat16 h0 = __float2bfloat16(v0), h1 = __float2bfloat16(v1);
    float r0 = v0 - __bfloat162float(h0);
    float r1 = v1 - __bfloat162float(h1);
    __nv_bfloat16 l0 = __float2bfloat16(r0), l1 = __float2bfloat16(r1);
    h = (uint32_t)__bfloat16_as_ushort(h0) | ((uint32_t)__bfloat16_as_ushort(h1) << 16);
    l = (uint32_t)__bfloat16_as_ushort(l0) | ((uint32_t)__bfloat16_as_ushort(l1) << 16);
}

// ======================= gather (fp32 + bf16 hi/lo) ==========================
__global__ void k_gather2(const float* __restrict__ emb, const int* __restrict__ x,
                          float* __restrict__ outf,
                          __nv_bfloat16* __restrict__ hb, int loOff, int n)
{
    int t = blockIdx.x * blockDim.x + threadIdx.x;
    if (t >= n * 32) return;
    int r = t >> 5, c = t & 31;
    float4 v = ((const float4*)emb)[(size_t)x[r] * 32 + c];
    ((float4*)outf)[t] = v;
    uint32_t h0, l0, h1, l1;
    bfsplit2(v.x, v.y, h0, l0);
    bfsplit2(v.z, v.w, h1, l1);
    size_t o = ((size_t)r * H + c * 4) >> 1;   // uint32 units (2 bf16)
    ((uint32_t*)hb)[o]     = h0;
    ((uint32_t*)hb)[o + 1] = h1;
    ((uint32_t*)(hb + loOff))[o]     = l0;
    ((uint32_t*)(hb + loOff))[o + 1] = l1;
}

// ======================= CSR build (merged) ==================================
__global__ void k_count_all(const int* __restrict__ ug_dst, const int* __restrict__ gi_src,
                            const int* __restrict__ ui_src, const int* __restrict__ ui_dst,
                            int* __restrict__ ib)
{
    int t = blockIdx.x * blockDim.x + threadIdx.x;
    if (t < E_UG) atomicAdd(&ib[OI_CNT_G1 + ug_dst[t]], 1);
    else if (t < E_UG + E_GI) atomicAdd(&ib[OI_CNT_G2 + gi_src[t - E_UG]], 1);
    else if (t < E_UG + E_GI + E_UI) atomicAdd(&ib[OI_CNT_U + ui_src[t - E_UG - E_GI]], 1);
    else if (t < E_UG + E_GI + 2*E_UI) atomicAdd(&ib[OI_CNT_I + ui_dst[t - E_UG - E_GI - E_UI]], 1);
}

__global__ void k_scan4(int* __restrict__ ib)
{
    const int* cnt; int* rp; int* cur; int n;
    switch (blockIdx.x) {
        case 0: cnt = ib + OI_CNT_G1; rp = ib + OI_RP_G1; cur = ib + OI_CUR_G1; n = NG; break;
        case 1: cnt = ib + OI_CNT_G2; rp = ib + OI_RP_G2; cur = ib + OI_CUR_G2; n = NG; break;
        case 2: cnt = ib + OI_CNT_U;  rp = ib + OI_RP_U;  cur = ib + OI_CUR_U;  n = NU; break;
        default: cnt = ib + OI_CNT_I; rp = ib + OI_RP_I;  cur = ib + OI_CUR_I;  n = NI; break;
    }
    __shared__ int ssum[1024];
    const int t = threadIdx.x;
    const int chunk = (n + 1023) / 1024;
    int beg = t * chunk;
    int end = beg + chunk; if (end > n) end = n;
    if (beg > n) beg = n;
    int s = 0;
    for (int i = beg; i < end; i++) s += cnt[i];
    ssum[t] = s;
    __syncthreads();
    for (int off = 1; off < 1024; off <<= 1) {
        int v = (t >= off) ? ssum[t - off] : 0;
        __syncthreads();
        ssum[t] += v;
        __syncthreads();
    }
    int prefix = (t == 0) ? 0 : ssum[t - 1];
    for (int i = beg; i < end; i++) {
        rp[i]  = prefix;
        cur[i] = prefix;
        prefix += cnt[i];
    }
    if (t == 1023) rp[n] = ssum[1023];
}

__global__ void k_bucket_all(const int* __restrict__ ug_src, const int* __restrict__ ug_dst,
                             const int* __restrict__ ui_src, const int* __restrict__ ui_dst,
                             const int* __restrict__ gi_src, const int* __restrict__ gi_dst,
                             int* __restrict__ ib)
{
    int t = blockIdx.x * blockDim.x + threadIdx.x;
    if (t < E_UG) {
        int p = atomicAdd(&ib[OI_CUR_G1 + ug_dst[t]], 1);
        ib[OI_COL_G1 + p] = ug_src[t];
    } else if (t < E_UG + E_GI) {
        int e = t - E_UG;
        int p = atomicAdd(&ib[OI_CUR_G2 + gi_src[e]], 1);
        ib[OI_COL_G2 + p] = gi_dst[e];
    } else if (t < E_UG + E_GI + E_UI) {
        int e = t - E_UG - E_GI;
        int p = atomicAdd(&ib[OI_CUR_U + ui_src[e]], 1);
        ib[OI_COL_U + p] = ui_dst[e];
    } else if (t < E_UG + E_GI + 2*E_UI) {
        int e = t - E_UG - E_GI - E_UI;
        int p = atomicAdd(&ib[OI_CUR_I + ui_dst[e]], 1);
        ib[OI_COL_I + p] = ui_src[e];
    }
}

// ======================= segment mean -> bf16 hi/lo ==========================
// 4-wide unrolled edge loop: batch independent col loads, then feature loads,
// so the col->feat dependent chain overlaps across 4 edges (MLP=4).
__device__ __forceinline__ void agg_row(const int* __restrict__ rp, const int* __restrict__ col,
                                        const float* __restrict__ feat,
                                        __nv_bfloat16* __restrict__ hb, int loOff,
                                        int row, int lane)
{
    int beg = rp[row], end = rp[row + 1];
    float4 acc = make_float4(0.f, 0.f, 0.f, 0.f);
    const float4* fv = (const float4*)feat;
    int e = beg;
    for (; e + 4 <= end; e += 4) {
        int s0 = __ldg(&col[e + 0]);
        int s1 = __ldg(&col[e + 1]);
        int s2 = __ldg(&col[e + 2]);
        int s3 = __ldg(&col[e + 3]);
        float4 v0 = __ldg(&fv[(size_t)s0 * 32 + lane]);
        float4 v1 = __ldg(&fv[(size_t)s1 * 32 + lane]);
        float4 v2 = __ldg(&fv[(size_t)s2 * 32 + lane]);
        float4 v3 = __ldg(&fv[(size_t)s3 * 32 + lane]);
        acc.x += v0.x + v1.x + v2.x + v3.x;
        acc.y += v0.y + v1.y + v2.y + v3.y;
        acc.z += v0.z + v1.z + v2.z + v3.z;
        acc.w += v0.w + v1.w + v2.w + v3.w;
    }
    for (; e < end; e++) {
        int s = __ldg(&col[e]);
        float4 v = __ldg(&fv[(size_t)s * 32 + lane]);
        acc.x += v.x; acc.y += v.y; acc.z += v.z; acc.w += v.w;
    }
    float inv = (end > beg) ? 1.f / (float)(end - beg) : 0.f;
    acc.x *= inv; acc.y *= inv; acc.z *= inv; acc.w *= inv;
    uint32_t h0, l0, h1, l1;
    bfsplit2(acc.x, acc.y, h0, l0);
    bfsplit2(acc.z, acc.w, h1, l1);
    size_t o = ((size_t)row * H + lane * 4) >> 1;
    ((uint32_t*)hb)[o]     = h0;
    ((uint32_t*)hb)[o + 1] = h1;
    ((uint32_t*)(hb + loOff))[o]     = l0;
    ((uint32_t*)(hb + loOff))[o + 1] = l1;
}

// layer-1 aggregations: AIU (items->users), AUI (users->items), AUG, AIG
__global__ void k_agg_all(const int* __restrict__ ib, const float* __restrict__ fb,
                          __nv_bfloat16* __restrict__ bb)
{
    int w = (int)((blockIdx.x * blockDim.x + threadIdx.x) >> 5);
    int lane = threadIdx.x & 31;
    if (w < NU)
        agg_row(ib + OI_RP_U, ib + OI_COL_U, fb + OF_HI, bb + OB_AIU, NU*H, w, lane);
    else if (w < NU + NI)
        agg_row(ib + OI_RP_I, ib + OI_COL_I, fb + OF_HU, bb + OB_AUI, NI*H, w - NU, lane);
    else if (w < NU + NI + NG)
        agg_row(ib + OI_RP_G1, ib + OI_COL_G1, fb + OF_HU, bb + OB_AUG, NG*H, w - NU - NI, lane);
    else if (w < NU + NI + 2*NG)
        agg_row(ib + OI_RP_G2, ib + OI_COL_G2, fb + OF_HI, bb + OB_AIG, NG*H, w - NU - NI - NG, lane);
}

// layer-2 aggregations: BUG (users->groups of HU1), BIG (items->groups of HI1)
__global__ void k_agg_all2(const int* __restrict__ ib, const float* __restrict__ fb,
                           __nv_bfloat16* __restrict__ bb)
{
    int w = (int)((blockIdx.x * blockDim.x + threadIdx.x) >> 5);
    int lane = threadIdx.x & 31;
    if (w < NG)
        agg_row(ib + OI_RP_G1, ib + OI_COL_G1, fb + OF_HU1, bb + OB_BUG, NG*H, w, lane);
    else if (w < 2*NG)
        agg_row(ib + OI_RP_G2, ib + OI_COL_G2, fb + OF_HI1, bb + OB_BIG, NG*H, w - NG, lane);
}

// ======================= weight prep =========================================
__global__ void k_wcomb(const float* __restrict__ W1r, const float* __restrict__ b1,
                        const float* __restrict__ W2r, const float* __restrict__ b2)
{
    int i = blockIdx.x * blockDim.x + threadIdx.x;
    float* Wc = g_f + OF_WC;
    float* bc = g_f + OF_BC;
    if (i < HH) {
        Wc[0*HH + i] = W1r[1*HH + i] + W1r[3*HH + i];
        Wc[1*HH + i] = W1r[2*HH + i] + W1r[4*HH + i];
        Wc[2*HH + i] = W2r[0*HH + i] + W2r[5*HH + i];
    }
    if (i < H) {
        bc[0*H + i] = b1[1*H + i] + b1[3*H + i];
        bc[1*H + i] = b1[2*H + i] + b1[4*H + i];
        bc[2*H + i] = b1[0*H + i] + b1[5*H + i];
        bc[3*H + i] = b2[0*H + i] + b2[5*H + i];
    }
}

// transpose+split 9 HxH weights into Bt [n][k] hi/lo bf16
__global__ void __launch_bounds__(256)
k_splitW(const float* __restrict__ W1l, const float* __restrict__ W2l,
         const float* __restrict__ Wc, __nv_bfloat16* __restrict__ dst9)
{
    const float* src;
    switch (blockIdx.z) {
        case 0: src = W1l + 3*HH; break;
        case 1: src = Wc  + 0*HH; break;
        case 2: src = W1l + 2*HH; break;
        case 3: src = Wc  + 1*HH; break;
        case 4: src = W1l + 0*HH; break;
        case 5: src = W1l + 5*HH; break;
        case 6: src = W2l + 0*HH; break;
        case 7: src = Wc  + 2*HH; break;
        default: src = W2l + 5*HH; break;
    }
    __nv_bfloat16* hi = dst9 + (size_t)blockIdx.z * 2 * HH;
    __nv_bfloat16* lo = hi + HH;
    __shared__ float t[32][33];
    int nblk = blockIdx.x * 32;
    int kblk = blockIdx.y * 32;
    int tx = threadIdx.x, ty = threadIdx.y;
#pragma unroll
    for (int i = ty; i < 32; i += 8)
        t[i][tx] = src[(size_t)(kblk + i) * H + nblk + tx];
    __syncthreads();
#pragma unroll
    for (int i = ty; i < 32; i += 8) {
        float x = t[tx][i];
        __nv_bfloat16 h = __float2bfloat16(x);
        size_t o = (size_t)(nblk + i) * H + kblk + tx;
        hi[o] = h;
        lo[o] = __float2bfloat16(x - __bfloat162float(h));
    }
}

// pred_W [H, NI] fp32 -> [NI, H] bf16 hi/lo (transposed, K contiguous)
__global__ void __launch_bounds__(256)
k_splitB(const float* __restrict__ W,
         __nv_bfloat16* __restrict__ hi, __nv_bfloat16* __restrict__ lo)
{
    __shared__ float t[32][33];
    int nblk = blockIdx.x * 32;
    int kblk = blockIdx.y * 32;
    int tx = threadIdx.x, ty = threadIdx.y;
#pragma unroll
    for (int i = ty; i < 32; i += 8)
        t[i][tx] = W[(size_t)(kblk + i) * NI + nblk + tx];
    __syncthreads();
#pragma unroll
    for (int i = ty; i < 32; i += 8) {
        float x = t[tx][i];
        __nv_bfloat16 h = __float2bfloat16(x);
        size_t o = (size_t)(nblk + i) * H + kblk + tx;
        hi[o] = h;
        lo[o] = __float2bfloat16(x - __bfloat162float(h));
    }
}

// ======================= HMMA layer GEMM (multi-term) ========================
#define PK   136
#define ROWB (PK * 2)          // 272 B per row
#define TILEB (128 * ROWB)     // 34816 B

#define GEMM_RELU 1
#define GEMM_BF16 2

struct GemmArgs {
    const __nv_bfloat16* Ah[3];
    const __nv_bfloat16* Al[3];
    const __nv_bfloat16* Wh[3];
    const float* bias;
    float* Cf;
    __nv_bfloat16* Cb;
    int M, nterms, flags, loOff;
};

#define SMEM_GH (4 * TILEB)    // 139264

__global__ void __launch_bounds__(256, 1)
k_gemm_h(GemmArgs g)
{
    extern __shared__ char sm[];
    const int tid  = threadIdx.x;
    const int wid  = tid >> 5;
    const int lane = tid & 31;
    const int wm   = wid >> 1;
    const int wn   = wid & 1;
    const int m0   = blockIdx.x * 128;

    const uint32_t sbase  = smem_u32(sm);
    const uint32_t a_loff = (uint32_t)(lane & 15) * ROWB + (uint32_t)(lane >> 4) * 16;
    const uint32_t b_loff = (uint32_t)(((lane >> 4) * 8) + (lane & 7)) * ROWB
                          + (uint32_t)((lane >> 3) & 1) * 16;

    float c[2][8][4];
#pragma unroll
    for (int i = 0; i < 2; i++)
#pragma unroll
        for (int j = 0; j < 8; j++)
#pragma unroll
            for (int q = 0; q < 4; q++) c[i][j][q] = 0.f;

#pragma unroll 1
    for (int t = 0; t < g.nterms; t++) {
        const uint4* wh = (const uint4*)g.Wh[t];
        const uint4* wl = (const uint4*)(g.Wh[t] + HH);
        const uint4* ah = (const uint4*)g.Ah[t];
        const uint4* al = (const uint4*)g.Al[t];
#pragma unroll 4
        for (int i = tid; i < 2048; i += 256) {
            int row = i >> 4, cq = i & 15;
            uint32_t so = (uint32_t)row * ROWB + cq * 16;
            *(uint4*)(sm + 0*TILEB + so) = __ldg(&wh[row * 16 + cq]);
            *(uint4*)(sm + 1*TILEB + so) = __ldg(&wl[row * 16 + cq]);
            uint4 va = make_uint4(0,0,0,0), vb = va;
            if (m0 + row < g.M) {
                size_t gi = (size_t)(m0 + row) * 16 + cq;
                va = __ldg(&ah[gi]);
                vb = __ldg(&al[gi]);
            }
            *(uint4*)(sm + 2*TILEB + so) = va;
            *(uint4*)(sm + 3*TILEB + so) = vb;
        }
        __syncthreads();
#pragma unroll 1
        for (int sp = 0; sp < 3; sp++) {
            uint32_t aB = sbase + (sp == 2 ? 3*TILEB : 2*TILEB)
                        + (uint32_t)wm * 32 * ROWB + a_loff;
            uint32_t bB = sbase + (sp == 1 ? 1*TILEB : 0)
                        + (uint32_t)wn * 64 * ROWB + b_loff;
#pragma unroll
            for (int ks = 0; ks < 8; ks++) {
                uint32_t a[2][4], b[4][4];
                LDSM4(a[0], aB + ks * 32);
                LDSM4(a[1], aB + ks * 32 + 16 * ROWB);
#pragma unroll
                for (int q = 0; q < 4; q++)
                    LDSM4(b[q], bB + ks * 32 + q * 16 * ROWB);
#pragma unroll
                for (int ma = 0; ma < 2; ma++)
#pragma unroll
                    for (int na = 0; na < 8; na++)
                        MMA_BF16(c[ma][na], a[ma],
                                 b[na >> 1][(na & 1) * 2], b[na >> 1][(na & 1) * 2 + 1]);
            }
        }
        __syncthreads();
    }

    const int gid = lane >> 2;
    const int tq  = (lane & 3) * 2;
    const bool relu = (g.flags & GEMM_RELU) != 0;
    const bool bfo  = (g.flags & GEMM_BF16) != 0;
#pragma unroll
    for (int ma = 0; ma < 2; ma++) {
#pragma unroll
        for (int na = 0; na < 8; na++) {
            int mrow = m0 + wm * 32 + ma * 16 + gid;
            int ncol = wn * 64 + na * 8 + tq;
            float2 bv = *(const float2*)(g.bias + ncol);
#pragma unroll
            for (int hrow = 0; hrow < 2; hrow++) {
                int mr = mrow + hrow * 8;
                if (mr >= g.M) continue;
                float v0 = c[ma][na][hrow*2 + 0] + bv.x;
                float v1 = c[ma][na][hrow*2 + 1] + bv.y;
                if (relu) { v0 = fmaxf(v0, 0.f); v1 = fmaxf(v1, 0.f); }
                if (bfo) {
                    uint32_t hw, lw;
                    bfsplit2(v0, v1, hw, lw);
                    *(uint32_t*)(g.Cb + (size_t)mr * H + ncol) = hw;
                    *(uint32_t*)(g.Cb + (size_t)g.loOff + (size_t)mr * H + ncol) = lw;
                } else {
                    *(float2*)(g.Cf + (size_t)mr * H + ncol) = make_float2(v0, v1);
                }
            }
        }
    }
}

// ======================= persistent pred GEMM ================================
// out[NG, NI] = REP[NG,128] @ PW[NI,128]^T + bias.
// 148 persistent CTAs; contiguous tile chunks (t -> m=t/NTN, n=t%NTN);
// A reloaded on m change (<=2 per CTA); B cp.async double-buffered.
#define NTN ((NI + 127) / 128)    // 157
#define NTM ((NG + 127) / 128)    // 40
#define NT_TOT (NTN * NTM)        // 6280
#define NCTA_PRED 148
#define SMEM_PRED (6 * TILEB)     // A hi/lo + 2 x B hi/lo = 208896

__device__ __forceinline__ void pred_loadA(uint32_t dstA, const uint4* gh, const uint4* gl,
                                           int m0_, int tid)
{
#pragma unroll 4
    for (int i = tid; i < 2048; i += 256) {
        int row = i >> 4, cq = i & 15;
        int gr = m0_ + row;
        int sz = (gr < NG) ? 16 : 0;
        if (gr >= NG) gr = NG - 1;
        uint32_t so = dstA + (uint32_t)row * ROWB + cq * 16;
        CPA16(so,         gh + (size_t)gr * 16 + cq, sz);
        CPA16(so + TILEB, gl + (size_t)gr * 16 + cq, sz);
    }
}

__device__ __forceinline__ void pred_loadB(uint32_t dstB, const uint4* gh, const uint4* gl,
                                           int n0_, int tid)
{
#pragma unroll 4
    for (int i = tid; i < 2048; i += 256) {
        int row = i >> 4, cq = i & 15;
        int gr = n0_ + row;
        int sz = (gr < NI) ? 16 : 0;
        if (gr >= NI) gr = NI - 1;
        uint32_t so = dstB + (uint32_t)row * ROWB + cq * 16;
        CPA16(so,         gh + (size_t)gr * 16 + cq, sz);
        CPA16(so + TILEB, gl + (size_t)gr * 16 + cq, sz);
    }
}

__global__ void __launch_bounds__(256, 1)
k_mma_pred(const __nv_bfloat16* __restrict__ Ahi, const __nv_bfloat16* __restrict__ Alo,
           const __nv_bfloat16* __restrict__ Bhi, const __nv_bfloat16* __restrict__ Blo,
           const float* __restrict__ bias, float* __restrict__ out)
{
    extern __shared__ char sm[];
    const int tid  = threadIdx.x;
    const int wid  = tid >> 5;
    const int lane = tid & 31;
    const int wm   = wid >> 1;
    const int wn   = wid & 1;

    const uint32_t sbase = smem_u32(sm);
    const uint32_t sB    = sbase + 2 * TILEB;

    const uint4* gAh = (const uint4*)Ahi;
    const uint4* gAl = (const uint4*)Alo;
    const uint4* gBh = (const uint4*)Bhi;
    const uint4* gBl = (const uint4*)Blo;

    const int beg = (int)((long long)blockIdx.x * NT_TOT / NCTA_PRED);
    const int end = (int)((long long)(blockIdx.x + 1) * NT_TOT / NCTA_PRED);

    const uint32_t a_loff = (uint32_t)(lane & 15) * ROWB + (uint32_t)(lane >> 4) * 16;
    const uint32_t b_loff = (uint32_t)(((lane >> 4) * 8) + (lane & 7)) * ROWB
                          + (uint32_t)((lane >> 3) & 1) * 16;
    const int gid = lane >> 2;
    const int tq  = (lane & 3) * 2;

    int cur_m = -1;
    int buf = 0;

#pragma unroll 1
    for (int t = beg; t < end; ++t) {
        int tm = t / NTN, tn = t - tm * NTN;
        if (tm != cur_m) {
            // drain any in-flight prefetch, load A(tm) + B(t) into buf 0
            CP_WAIT0();
            __syncthreads();
            pred_loadA(sbase, gAh, gAl, tm * 128, tid);
            pred_loadB(sB, gBh, gBl, tn * 128, tid);
            CP_COMMIT();
            cur_m = tm;
            buf = 0;
            if (t + 1 < end && (t + 1) / NTN == cur_m) {
                pred_loadB(sB + 2 * TILEB, gBh, gBl, (tn + 1) * 128, tid);
                CP_COMMIT();
                CP_WAIT1();
            } else {
                CP_WAIT0();
            }
            __syncthreads();
        } else {
            // B(t) already resident in buf; prefetch B(t+1) into other buffer
            if (t + 1 < end && (t + 1) / NTN == cur_m) {
                pred_loadB(sB + (uint32_t)(buf ^ 1) * 2 * TILEB, gBh, gBl, (tn + 1) * 128, tid);
                CP_COMMIT();
                CP_WAIT1();
            } else {
                CP_WAIT0();
            }
            __syncthreads();
        }

        float c[2][8][4];
#pragma unroll
        for (int i = 0; i < 2; i++)
#pragma unroll
            for (int j = 0; j < 8; j++)
#pragma unroll
                for (int q = 0; q < 4; q++) c[i][j][q] = 0.f;

        uint32_t curB = sB + (uint32_t)buf * 2 * TILEB;
#pragma unroll 1
        for (int sp = 0; sp < 3; sp++) {
            uint32_t aB = sbase + (sp == 2 ? TILEB : 0) + (uint32_t)wm * 32 * ROWB + a_loff;
            uint32_t bB = curB + (sp == 1 ? TILEB : 0) + (uint32_t)wn * 64 * ROWB + b_loff;
#pragma unroll
            for (int ks = 0; ks < 8; ks++) {
                uint32_t a[2][4], b[4][4];
                LDSM4(a[0], aB + ks * 32);
                LDSM4(a[1], aB + ks * 32 + 16 * ROWB);
#pragma unroll
                for (int q = 0; q < 4; q++)
                    LDSM4(b[q], bB + ks * 32 + q * 16 * ROWB);
#pragma unroll
                for (int ma = 0; ma < 2; ma++)
#pragma unroll
                    for (int na = 0; na < 8; na++)
                        MMA_BF16(c[ma][na], a[ma],
                                 b[na >> 1][(na & 1) * 2], b[na >> 1][(na & 1) * 2 + 1]);
            }
        }

        // epilogue
        int m0_ = tm * 128, n0_ = tn * 128;
#pragma unroll
        for (int ma = 0; ma < 2; ma++) {
#pragma unroll
            for (int na = 0; na < 8; na++) {
                int mrow = m0_ + wm * 32 + ma * 16 + gid;
                int ncol = n0_ + wn * 64 + na * 8 + tq;
                if (ncol >= NI) continue;
                float2 bv = *(const float2*)(bias + ncol);
                if (mrow < NG) {
                    float2 v = make_float2(c[ma][na][0] + bv.x, c[ma][na][1] + bv.y);
                    *(float2*)(out + (size_t)mrow * NI + ncol) = v;
                }
                if (mrow + 8 < NG) {
                    float2 v = make_float2(c[ma][na][2] + bv.x, c[ma][na][3] + bv.y);
                    *(float2*)(out + (size_t)(mrow + 8) * NI + ncol) = v;
                }
            }
        }
        __syncthreads();
        buf ^= 1;
    }
}

// ---------------------------------------------------------------------------
extern "C" void kernel_launch(void* const* d_in, const int* in_sizes, int n_in,
                              void* d_out, int out_size)
{
    const int*   x_user   = (const int*)  d_in[1];
    const int*   x_item   = (const int*)  d_in[2];
    const float* emb_user = (const float*)d_in[4];
    const float* emb_item = (const float*)d_in[5];
    const float* W1l      = (const float*)d_in[6];
    const float* W1r      = (const float*)d_in[7];
    const float* b1       = (const float*)d_in[8];
    const float* W2l      = (const float*)d_in[9];
    const float* W2r      = (const float*)d_in[10];
    const float* b2       = (const float*)d_in[11];
    const float* pred_W   = (const float*)d_in[12];
    const float* pred_b   = (const float*)d_in[13];
    const int*   ug_src   = (const int*)  d_in[14];
    const int*   ug_dst   = (const int*)  d_in[15];
    const int*   ui_src   = (const int*)  d_in[16];
    const int*   ui_dst   = (const int*)  d_in[17];
    const int*   gi_src   = (const int*)  d_in[18];
    const int*   gi_dst   = (const int*)  d_in[19];
    float* out = (float*)d_out;

    float* fb = nullptr; int* ib = nullptr; __nv_bfloat16* bb = nullptr;
    cudaGetSymbolAddress((void**)&fb, g_f);
    cudaGetSymbolAddress((void**)&ib, g_i);
    cudaGetSymbolAddress((void**)&bb, g_bf);

    cudaFuncSetAttribute(k_gemm_h, cudaFuncAttributeMaxDynamicSharedMemorySize, SMEM_GH);
    cudaFuncSetAttribute(k_mma_pred, cudaFuncAttributeMaxDynamicSharedMemorySize, SMEM_PRED);

    cudaMemsetAsync(ib + OI_CNT_G1, 0, (size_t)CNT_TOTAL * sizeof(int));

    // weight prep
    k_splitB<<<dim3(NI / 32, H / 32), dim3(32, 8)>>>(pred_W, bb + OB_PW, bb + OB_PW + NI*H);
    k_wcomb<<<(HH + 255) / 256, 256>>>(W1r, b1, W2r, b2);
    k_splitW<<<dim3(4, 4, 9), dim3(32, 8)>>>(W1l, W2l, fb + OF_WC, bb + OB_W);

    // embedding gathers (fp32 + bf16 hi/lo)
    k_gather2<<<(NU * 32 + 255) / 256, 256>>>(emb_user, x_user, fb + OF_HU,
                                              bb + OB_HUe, NU*H, NU);
    k_gather2<<<(NI * 32 + 255) / 256, 256>>>(emb_item, x_item, fb + OF_HI,
                                              bb + OB_HIe, NI*H, NI);

    // CSR build
    {
        int tot = E_UG + E_GI + 2 * E_UI;
        k_count_all<<<(tot + 255) / 256, 256>>>(ug_dst, gi_src, ui_src, ui_dst, ib);
        k_scan4<<<4, 1024>>>(ib);
        k_bucket_all<<<(tot + 255) / 256, 256>>>(ug_src, ug_dst, ui_src, ui_dst,
                                                 gi_src, gi_dst, ib);
    }

    // layer-1 aggregations -> bf16 hi/lo
    {
        int warps = NU + NI + 2 * NG;
        k_agg_all<<<(warps + 7) / 8, 256>>>(ib, fb, bb);
    }

    // layer-1 GEMMs
    {
        GemmArgs a = {};
        a.Ah[0] = bb + OB_AIU;  a.Al[0] = bb + OB_AIU + NU*H;  a.Wh[0] = bb + OB_W + SL_W1L3*2*HH;
        a.Ah[1] = bb + OB_HUe;  a.Al[1] = bb + OB_HUe + NU*H;  a.Wh[1] = bb + OB_W + SL_WC0*2*HH;
        a.bias = fb + OF_BC + 0*H;
        a.Cf = fb + OF_HU1; a.M = NU; a.nterms = 2; a.flags = GEMM_RELU;
        k_gemm_h<<<(NU + 127) / 128, 256, SMEM_GH>>>(a);
    }
    {
        GemmArgs a = {};
        a.Ah[0] = bb + OB_AUI;  a.Al[0] = bb + OB_AUI + NI*H;  a.Wh[0] = bb + OB_W + SL_W1L2*2*HH;
        a.Ah[1] = bb + OB_HIe;  a.Al[1] = bb + OB_HIe + NI*H;  a.Wh[1] = bb + OB_W + SL_WC1*2*HH;
        a.bias = fb + OF_BC + 1*H;
        a.Cf = fb + OF_HI1; a.M = NI; a.nterms = 2; a.flags = GEMM_RELU;
        k_gemm_h<<<(NI + 127) / 128, 256, SMEM_GH>>>(a);
    }
    {
        GemmArgs a = {};
        a.Ah[0] = bb + OB_AUG;  a.Al[0] = bb + OB_AUG + NG*H;  a.Wh[0] = bb + OB_W + SL_W1L0*2*HH;
        a.Ah[1] = bb + OB_AIG;  a.Al[1] = bb + OB_AIG + NG*H;  a.Wh[1] = bb + OB_W + SL_W1L5*2*HH;
        a.bias = fb + OF_BC + 2*H;
        a.Cb = bb + OB_HG1; a.loOff = NG*H;
        a.M = NG; a.nterms = 2; a.flags = GEMM_RELU | GEMM_BF16;
        k_gemm_h<<<(NG + 127) / 128, 256, SMEM_GH>>>(a);
    }

    // layer-2 aggregations
    k_agg_all2<<<(2 * NG + 7) / 8, 256>>>(ib, fb, bb);

    // layer-2 group GEMM (3 terms) -> REP bf16 hi/lo
    {
        GemmArgs a = {};
        a.Ah[0] = bb + OB_BUG;  a.Al[0] = bb + OB_BUG + NG*H;  a.Wh[0] = bb + OB_W + SL_W2L0*2*HH;
        a.Ah[1] = bb + OB_HG1;  a.Al[1] = bb + OB_HG1 + NG*H;  a.Wh[1] = bb + OB_W + SL_WC2*2*HH;
        a.Ah[2] = bb + OB_BIG;  a.Al[2] = bb + OB_BIG + NG*H;  a.Wh[2] = bb + OB_W + SL_W2L5*2*HH;
        a.bias = fb + OF_BC + 3*H;
        a.Cb = bb + OB_REP; a.loOff = NG*H;
        a.M = NG; a.nterms = 3; a.flags = GEMM_RELU | GEMM_BF16;
        k_gemm_h<<<(NG + 127) / 128, 256, SMEM_GH>>>(a);
    }

    // persistent prediction GEMM
    k_mma_pred<<<NCTA_PRED, 256, SMEM_PRED>>>(bb + OB_REP, bb + OB_REP + NG*H,
                                              bb + OB_PW,  bb + OB_PW + NI*H,
                                              pred_b, out);
    (void)in_sizes; (void)n_in; (void)out_size;
}

// round 6
// speedup vs baseline: 1.6630x; 1.0618x over previous
#include <cuda_runtime.h>
#include <cuda_bf16.h>
#include <cstdint>

// ----------------------------------------------------------------------------
// BaseGR hetero-SAGE on GB300 — R6.
// vs R5: layer-1 GEMMs replaced by ONE persistent kernel (k_gemm_l):
// 148 CTAs split across the 3 GEMM jobs; W tiles SMEM-resident per CTA;
// 64-row A sub-tiles streamed via cp.async double buffer (~95% tensor eff).
// Gather launches merged. Everything else unchanged from R5.
// ----------------------------------------------------------------------------

#define NG 5000
#define NU 100000
#define NI 20000
#define H 128
#define HH (H*H)
#define E_UG 300000
#define E_UI 600000
#define E_GI 200000

// ---------------- fp32 scratch ----------------
#define OF_HU  0
#define OF_HI  (OF_HU  + NU*H)
#define OF_HU1 (OF_HI  + NI*H)
#define OF_HI1 (OF_HU1 + NU*H)
#define OF_WC  (OF_HI1 + NI*H)
#define OF_BC  (OF_WC  + 3*HH)
#define F_TOTAL (OF_BC + 4*H)
__device__ float g_f[F_TOTAL];

// ---------------- bf16 scratch (hi plane then lo plane for each) -------------
#define OB_HUe 0
#define OB_HIe (OB_HUe + 2*NU*H)
#define OB_AIU (OB_HIe + 2*NI*H)
#define OB_AUI (OB_AIU + 2*NU*H)
#define OB_AUG (OB_AUI + 2*NI*H)
#define OB_AIG (OB_AUG + 2*NG*H)
#define OB_HG1 (OB_AIG + 2*NG*H)
#define OB_BUG (OB_HG1 + 2*NG*H)
#define OB_BIG (OB_BUG + 2*NG*H)
#define OB_REP (OB_BIG + 2*NG*H)
#define OB_PW  (OB_REP + 2*NG*H)
#define OB_W   (OB_PW  + 2*NI*H)
#define B_TOTAL (OB_W + 18*HH)
__device__ __nv_bfloat16 g_bf[B_TOTAL];

// weight slots in OB_W (each slot: hi HH then lo HH)
#define SL_W1L3 0
#define SL_WC0  1
#define SL_W1L2 2
#define SL_WC1  3
#define SL_W1L0 4
#define SL_W1L5 5
#define SL_W2L0 6
#define SL_WC2  7
#define SL_W2L5 8

// ---------------- int scratch ----------------
#define OI_CNT_G1 0
#define OI_CNT_G2 (OI_CNT_G1 + NG)
#define OI_CNT_U  (OI_CNT_G2 + NG)
#define OI_CNT_I  (OI_CNT_U  + NU)
#define CNT_TOTAL (OI_CNT_I  + NI)
#define OI_RP_G1  CNT_TOTAL
#define OI_RP_G2  (OI_RP_G1 + NG + 1)
#define OI_RP_U   (OI_RP_G2 + NG + 1)
#define OI_RP_I   (OI_RP_U  + NU + 1)
#define OI_CUR_G1 (OI_RP_I  + NI + 1)
#define OI_CUR_G2 (OI_CUR_G1 + NG)
#define OI_CUR_U  (OI_CUR_G2 + NG)
#define OI_CUR_I  (OI_CUR_U  + NU)
#define OI_COL_G1 (OI_CUR_I  + NI)
#define OI_COL_G2 (OI_COL_G1 + E_UG)
#define OI_COL_U  (OI_COL_G2 + E_GI)
#define OI_COL_I  (OI_COL_U  + E_UI)
#define I_TOTAL   (OI_COL_I  + E_UI)
__device__ int g_i[I_TOTAL];

// ======================= helpers =============================================
__device__ __forceinline__ uint32_t smem_u32(const void* p) {
    uint32_t a;
    asm("{ .reg .u64 t; cvta.to.shared.u64 t, %1; cvt.u32.u64 %0, t; }"
        : "=r"(a) : "l"(p));
    return a;
}

#define LDSM4(r, addr) \
    asm volatile("ldmatrix.sync.aligned.m8n8.x4.shared.b16 {%0,%1,%2,%3}, [%4];" \
                 : "=r"((r)[0]), "=r"((r)[1]), "=r"((r)[2]), "=r"((r)[3]) \
                 : "r"(addr))

#define MMA_BF16(c, a, b0, b1) \
    asm volatile("mma.sync.aligned.m16n8k16.row.col.f32.bf16.bf16.f32 " \
                 "{%0,%1,%2,%3}, {%4,%5,%6,%7}, {%8,%9}, {%0,%1,%2,%3};" \
                 : "+f"((c)[0]), "+f"((c)[1]), "+f"((c)[2]), "+f"((c)[3]) \
                 : "r"((a)[0]), "r"((a)[1]), "r"((a)[2]), "r"((a)[3]), \
                   "r"(b0), "r"(b1))

#define CPA16(dst, src, sz) \
    asm volatile("cp.async.cg.shared.global [%0], [%1], 16, %2;" \
                 :: "r"(dst), "l"(src), "r"(sz))
#define CP_COMMIT() asm volatile("cp.async.commit_group;" ::: "memory")
#define CP_WAIT0()  asm volatile("cp.async.wait_group 0;" ::: "memory")
#define CP_WAIT1()  asm volatile("cp.async.wait_group 1;" ::: "memory")

// split v0,v1 into packed bf16 hi / lo words
__device__ __forceinline__ void bfsplit2(float v0, float v1, uint32_t& h, uint32_t& l)
{
    __nv_bfloat16 h0 = __float2bfloat16(v0), h1 = __float2bfloat16(v1);
    float r0 = v0 - __bfloat162float(h0);
    float r1 = v1 - __bfloat162float(h1);
    __nv_bfloat16 l0 = __float2bfloat16(r0), l1 = __float2bfloat16(r1);
    h = (uint32_t)__bfloat16_as_ushort(h0) | ((uint32_t)__bfloat16_as_ushort(h1) << 16);
    l = (uint32_t)__bfloat16_as_ushort(l0) | ((uint32_t)__bfloat16_as_ushort(l1) << 16);
}

// ======================= merged gather (fp32 + bf16 hi/lo) ===================
__global__ void k_gather2m(const float* __restrict__ emb_u, const int* __restrict__ x_u,
                           const float* __restrict__ emb_i, const int* __restrict__ x_i,
                           float* __restrict__ fb, __nv_bfloat16* __restrict__ bbuf)
{
    int t = blockIdx.x * blockDim.x + threadIdx.x;
    const float* emb; const int* x;
    float* outf; __nv_bfloat16* hb; int loOff; int r;
    if (t < NU * 32) {
        emb = emb_u; x = x_u; outf = fb + OF_HU; hb = bbuf + OB_HUe; loOff = NU * H;
        r = t >> 5;
    } else if (t < (NU + NI) * 32) {
        t -= NU * 32;
        emb = emb_i; x = x_i; outf = fb + OF_HI; hb = bbuf + OB_HIe; loOff = NI * H;
        r = t >> 5;
    } else return;
    int c = t & 31;
    float4 v = ((const float4*)emb)[(size_t)x[r] * 32 + c];
    ((float4*)outf)[(size_t)r * 32 + c] = v;
    uint32_t h0, l0, h1, l1;
    bfsplit2(v.x, v.y, h0, l0);
    bfsplit2(v.z, v.w, h1, l1);
    size_t o = ((size_t)r * H + c * 4) >> 1;
    ((uint32_t*)hb)[o]     = h0;
    ((uint32_t*)hb)[o + 1] = h1;
    ((uint32_t*)(hb + loOff))[o]     = l0;
    ((uint32_t*)(hb + loOff))[o + 1] = l1;
}

// ======================= CSR build (merged) ==================================
__global__ void k_count_all(const int* __restrict__ ug_dst, const int* __restrict__ gi_src,
                            const int* __restrict__ ui_src, const int* __restrict__ ui_dst,
                            int* __restrict__ ib)
{
    int t = blockIdx.x * blockDim.x + threadIdx.x;
    if (t < E_UG) atomicAdd(&ib[OI_CNT_G1 + ug_dst[t]], 1);
    else if (t < E_UG + E_GI) atomicAdd(&ib[OI_CNT_G2 + gi_src[t - E_UG]], 1);
    else if (t < E_UG + E_GI + E_UI) atomicAdd(&ib[OI_CNT_U + ui_src[t - E_UG - E_GI]], 1);
    else if (t < E_UG + E_GI + 2*E_UI) atomicAdd(&ib[OI_CNT_I + ui_dst[t - E_UG - E_GI - E_UI]], 1);
}

__global__ void k_scan4(int* __restrict__ ib)
{
    const int* cnt; int* rp; int* cur; int n;
    switch (blockIdx.x) {
        case 0: cnt = ib + OI_CNT_G1; rp = ib + OI_RP_G1; cur = ib + OI_CUR_G1; n = NG; break;
        case 1: cnt = ib + OI_CNT_G2; rp = ib + OI_RP_G2; cur = ib + OI_CUR_G2; n = NG; break;
        case 2: cnt = ib + OI_CNT_U;  rp = ib + OI_RP_U;  cur = ib + OI_CUR_U;  n = NU; break;
        default: cnt = ib + OI_CNT_I; rp = ib + OI_RP_I;  cur = ib + OI_CUR_I;  n = NI; break;
    }
    __shared__ int ssum[1024];
    const int t = threadIdx.x;
    const int chunk = (n + 1023) / 1024;
    int beg = t * chunk;
    int end = beg + chunk; if (end > n) end = n;
    if (beg > n) beg = n;
    int s = 0;
    for (int i = beg; i < end; i++) s += cnt[i];
    ssum[t] = s;
    __syncthreads();
    for (int off = 1; off < 1024; off <<= 1) {
        int v = (t >= off) ? ssum[t - off] : 0;
        __syncthreads();
        ssum[t] += v;
        __syncthreads();
    }
    int prefix = (t == 0) ? 0 : ssum[t - 1];
    for (int i = beg; i < end; i++) {
        rp[i]  = prefix;
        cur[i] = prefix;
        prefix += cnt[i];
    }
    if (t == 1023) rp[n] = ssum[1023];
}

__global__ void k_bucket_all(const int* __restrict__ ug_src, const int* __restrict__ ug_dst,
                             const int* __restrict__ ui_src, const int* __restrict__ ui_dst,
                             const int* __restrict__ gi_src, const int* __restrict__ gi_dst,
                             int* __restrict__ ib)
{
    int t = blockIdx.x * blockDim.x + threadIdx.x;
    if (t < E_UG) {
        int p = atomicAdd(&ib[OI_CUR_G1 + ug_dst[t]], 1);
        ib[OI_COL_G1 + p] = ug_src[t];
    } else if (t < E_UG + E_GI) {
        int e = t - E_UG;
        int p = atomicAdd(&ib[OI_CUR_G2 + gi_src[e]], 1);
        ib[OI_COL_G2 + p] = gi_dst[e];
    } else if (t < E_UG + E_GI + E_UI) {
        int e = t - E_UG - E_GI;
        int p = atomicAdd(&ib[OI_CUR_U + ui_src[e]], 1);
        ib[OI_COL_U + p] = ui_dst[e];
    } else if (t < E_UG + E_GI + 2*E_UI) {
        int e = t - E_UG - E_GI - E_UI;
        int p = atomicAdd(&ib[OI_CUR_I + ui_dst[e]], 1);
        ib[OI_COL_I + p] = ui_src[e];
    }
}

// ======================= segment mean -> bf16 hi/lo ==========================
__device__ __forceinline__ void agg_row(const int* __restrict__ rp, const int* __restrict__ col,
                                        const float* __restrict__ feat,
                                        __nv_bfloat16* __restrict__ hb, int loOff,
                                        int row, int lane)
{
    int beg = rp[row], end = rp[row + 1];
    float4 acc = make_float4(0.f, 0.f, 0.f, 0.f);
    const float4* fv = (const float4*)feat;
    int e = beg;
    for (; e + 4 <= end; e += 4) {
        int s0 = __ldg(&col[e + 0]);
        int s1 = __ldg(&col[e + 1]);
        int s2 = __ldg(&col[e + 2]);
        int s3 = __ldg(&col[e + 3]);
        float4 v0 = __ldg(&fv[(size_t)s0 * 32 + lane]);
        float4 v1 = __ldg(&fv[(size_t)s1 * 32 + lane]);
        float4 v2 = __ldg(&fv[(size_t)s2 * 32 + lane]);
        float4 v3 = __ldg(&fv[(size_t)s3 * 32 + lane]);
        acc.x += v0.x + v1.x + v2.x + v3.x;
        acc.y += v0.y + v1.y + v2.y + v3.y;
        acc.z += v0.z + v1.z + v2.z + v3.z;
        acc.w += v0.w + v1.w + v2.w + v3.w;
    }
    for (; e < end; e++) {
        int s = __ldg(&col[e]);
        float4 v = __ldg(&fv[(size_t)s * 32 + lane]);
        acc.x += v.x; acc.y += v.y; acc.z += v.z; acc.w += v.w;
    }
    float inv = (end > beg) ? 1.f / (float)(end - beg) : 0.f;
    acc.x *= inv; acc.y *= inv; acc.z *= inv; acc.w *= inv;
    uint32_t h0, l0, h1, l1;
    bfsplit2(acc.x, acc.y, h0, l0);
    bfsplit2(acc.z, acc.w, h1, l1);
    size_t o = ((size_t)row * H + lane * 4) >> 1;
    ((uint32_t*)hb)[o]     = h0;
    ((uint32_t*)hb)[o + 1] = h1;
    ((uint32_t*)(hb + loOff))[o]     = l0;
    ((uint32_t*)(hb + loOff))[o + 1] = l1;
}

__global__ void k_agg_all(const int* __restrict__ ib, const float* __restrict__ fb,
                          __nv_bfloat16* __restrict__ bb)
{
    int w = (int)((blockIdx.x * blockDim.x + threadIdx.x) >> 5);
    int lane = threadIdx.x & 31;
    if (w < NU)
        agg_row(ib + OI_RP_U, ib + OI_COL_U, fb + OF_HI, bb + OB_AIU, NU*H, w, lane);
    else if (w < NU + NI)
        agg_row(ib + OI_RP_I, ib + OI_COL_I, fb + OF_HU, bb + OB_AUI, NI*H, w - NU, lane);
    else if (w < NU + NI + NG)
        agg_row(ib + OI_RP_G1, ib + OI_COL_G1, fb + OF_HU, bb + OB_AUG, NG*H, w - NU - NI, lane);
    else if (w < NU + NI + 2*NG)
        agg_row(ib + OI_RP_G2, ib + OI_COL_G2, fb + OF_HI, bb + OB_AIG, NG*H, w - NU - NI - NG, lane);
}

__global__ void k_agg_all2(const int* __restrict__ ib, const float* __restrict__ fb,
                           __nv_bfloat16* __restrict__ bb)
{
    int w = (int)((blockIdx.x * blockDim.x + threadIdx.x) >> 5);
    int lane = threadIdx.x & 31;
    if (w < NG)
        agg_row(ib + OI_RP_G1, ib + OI_COL_G1, fb + OF_HU1, bb + OB_BUG, NG*H, w, lane);
    else if (w < 2*NG)
        agg_row(ib + OI_RP_G2, ib + OI_COL_G2, fb + OF_HI1, bb + OB_BIG, NG*H, w - NG, lane);
}

// ======================= weight prep =========================================
__global__ void k_wcomb(const float* __restrict__ W1r, const float* __restrict__ b1,
                        const float* __restrict__ W2r, const float* __restrict__ b2)
{
    int i = blockIdx.x * blockDim.x + threadIdx.x;
    float* Wc = g_f + OF_WC;
    float* bc = g_f + OF_BC;
    if (i < HH) {
        Wc[0*HH + i] = W1r[1*HH + i] + W1r[3*HH + i];
        Wc[1*HH + i] = W1r[2*HH + i] + W1r[4*HH + i];
        Wc[2*HH + i] = W2r[0*HH + i] + W2r[5*HH + i];
    }
    if (i < H) {
        bc[0*H + i] = b1[1*H + i] + b1[3*H + i];
        bc[1*H + i] = b1[2*H + i] + b1[4*H + i];
        bc[2*H + i] = b1[0*H + i] + b1[5*H + i];
        bc[3*H + i] = b2[0*H + i] + b2[5*H + i];
    }
}

__global__ void __launch_bounds__(256)
k_splitW(const float* __restrict__ W1l, const float* __restrict__ W2l,
         const float* __restrict__ Wc, __nv_bfloat16* __restrict__ dst9)
{
    const float* src;
    switch (blockIdx.z) {
        case 0: src = W1l + 3*HH; break;
        case 1: src = Wc  + 0*HH; break;
        case 2: src = W1l + 2*HH; break;
        case 3: src = Wc  + 1*HH; break;
        case 4: src = W1l + 0*HH; break;
        case 5: src = W1l + 5*HH; break;
        case 6: src = W2l + 0*HH; break;
        case 7: src = Wc  + 2*HH; break;
        default: src = W2l + 5*HH; break;
    }
    __nv_bfloat16* hi = dst9 + (size_t)blockIdx.z * 2 * HH;
    __nv_bfloat16* lo = hi + HH;
    __shared__ float t[32][33];
    int nblk = blockIdx.x * 32;
    int kblk = blockIdx.y * 32;
    int tx = threadIdx.x, ty = threadIdx.y;
#pragma unroll
    for (int i = ty; i < 32; i += 8)
        t[i][tx] = src[(size_t)(kblk + i) * H + nblk + tx];
    __syncthreads();
#pragma unroll
    for (int i = ty; i < 32; i += 8) {
        float x = t[tx][i];
        __nv_bfloat16 h = __float2bfloat16(x);
        size_t o = (size_t)(nblk + i) * H + kblk + tx;
        hi[o] = h;
        lo[o] = __float2bfloat16(x - __bfloat162float(h));
    }
}

__global__ void __launch_bounds__(256)
k_splitB(const float* __restrict__ W,
         __nv_bfloat16* __restrict__ hi, __nv_bfloat16* __restrict__ lo)
{
    __shared__ float t[32][33];
    int nblk = blockIdx.x * 32;
    int kblk = blockIdx.y * 32;
    int tx = threadIdx.x, ty = threadIdx.y;
#pragma unroll
    for (int i = ty; i < 32; i += 8)
        t[i][tx] = W[(size_t)(kblk + i) * NI + nblk + tx];
    __syncthreads();
#pragma unroll
    for (int i = ty; i < 32; i += 8) {
        float x = t[tx][i];
        __nv_bfloat16 h = __float2bfloat16(x);
        size_t o = (size_t)(nblk + i) * H + kblk + tx;
        hi[o] = h;
        lo[o] = __float2bfloat16(x - __bfloat162float(h));
    }
}

// ======================= common GEMM constants ===============================
#define PK   136
#define ROWB (PK * 2)          // 272 B per row
#define TILEB (128 * ROWB)     // 34816 B
#define HTILE (64 * ROWB)      // 17408 B

#define GEMM_RELU 1
#define GEMM_BF16 2

// ======================= HMMA layer-2 GEMM (multi-term, small) ===============
struct GemmArgs {
    const __nv_bfloat16* Ah[3];
    const __nv_bfloat16* Al[3];
    const __nv_bfloat16* Wh[3];
    const float* bias;
    float* Cf;
    __nv_bfloat16* Cb;
    int M, nterms, flags, loOff;
};

#define SMEM_GH (4 * TILEB)    // 139264

__global__ void __launch_bounds__(256, 1)
k_gemm_h(GemmArgs g)
{
    extern __shared__ char sm[];
    const int tid  = threadIdx.x;
    const int wid  = tid >> 5;
    const int lane = tid & 31;
    const int wm   = wid >> 1;
    const int wn   = wid & 1;
    const int m0   = blockIdx.x * 128;

    const uint32_t sbase  = smem_u32(sm);
    const uint32_t a_loff = (uint32_t)(lane & 15) * ROWB + (uint32_t)(lane >> 4) * 16;
    const uint32_t b_loff = (uint32_t)(((lane >> 4) * 8) + (lane & 7)) * ROWB
                          + (uint32_t)((lane >> 3) & 1) * 16;

    float c[2][8][4];
#pragma unroll
    for (int i = 0; i < 2; i++)
#pragma unroll
        for (int j = 0; j < 8; j++)
#pragma unroll
            for (int q = 0; q < 4; q++) c[i][j][q] = 0.f;

#pragma unroll 1
    for (int t = 0; t < g.nterms; t++) {
        const uint4* wh = (const uint4*)g.Wh[t];
        const uint4* wl = (const uint4*)(g.Wh[t] + HH);
        const uint4* ah = (const uint4*)g.Ah[t];
        const uint4* al = (const uint4*)g.Al[t];
#pragma unroll 4
        for (int i = tid; i < 2048; i += 256) {
            int row = i >> 4, cq = i & 15;
            uint32_t so = (uint32_t)row * ROWB + cq * 16;
            *(uint4*)(sm + 0*TILEB + so) = __ldg(&wh[row * 16 + cq]);
            *(uint4*)(sm + 1*TILEB + so) = __ldg(&wl[row * 16 + cq]);
            uint4 va = make_uint4(0,0,0,0), vb = va;
            if (m0 + row < g.M) {
                size_t gi = (size_t)(m0 + row) * 16 + cq;
                va = __ldg(&ah[gi]);
                vb = __ldg(&al[gi]);
            }
            *(uint4*)(sm + 2*TILEB + so) = va;
            *(uint4*)(sm + 3*TILEB + so) = vb;
        }
        __syncthreads();
#pragma unroll 1
        for (int sp = 0; sp < 3; sp++) {
            uint32_t aB = sbase + (sp == 2 ? 3*TILEB : 2*TILEB)
                        + (uint32_t)wm * 32 * ROWB + a_loff;
            uint32_t bB = sbase + (sp == 1 ? 1*TILEB : 0)
                        + (uint32_t)wn * 64 * ROWB + b_loff;
#pragma unroll
            for (int ks = 0; ks < 8; ks++) {
                uint32_t a[2][4], b[4][4];
                LDSM4(a[0], aB + ks * 32);
                LDSM4(a[1], aB + ks * 32 + 16 * ROWB);
#pragma unroll
                for (int q = 0; q < 4; q++)
                    LDSM4(b[q], bB + ks * 32 + q * 16 * ROWB);
#pragma unroll
                for (int ma = 0; ma < 2; ma++)
#pragma unroll
                    for (int na = 0; na < 8; na++)
                        MMA_BF16(c[ma][na], a[ma],
                                 b[na >> 1][(na & 1) * 2], b[na >> 1][(na & 1) * 2 + 1]);
            }
        }
        __syncthreads();
    }

    const int gid = lane >> 2;
    const int tq  = (lane & 3) * 2;
    const bool relu = (g.flags & GEMM_RELU) != 0;
    const bool bfo  = (g.flags & GEMM_BF16) != 0;
#pragma unroll
    for (int ma = 0; ma < 2; ma++) {
#pragma unroll
        for (int na = 0; na < 8; na++) {
            int mrow = m0 + wm * 32 + ma * 16 + gid;
            int ncol = wn * 64 + na * 8 + tq;
            float2 bv = *(const float2*)(g.bias + ncol);
#pragma unroll
            for (int hrow = 0; hrow < 2; hrow++) {
                int mr = mrow + hrow * 8;
                if (mr >= g.M) continue;
                float v0 = c[ma][na][hrow*2 + 0] + bv.x;
                float v1 = c[ma][na][hrow*2 + 1] + bv.y;
                if (relu) { v0 = fmaxf(v0, 0.f); v1 = fmaxf(v1, 0.f); }
                if (bfo) {
                    uint32_t hw, lw;
                    bfsplit2(v0, v1, hw, lw);
                    *(uint32_t*)(g.Cb + (size_t)mr * H + ncol) = hw;
                    *(uint32_t*)(g.Cb + (size_t)g.loOff + (size_t)mr * H + ncol) = lw;
                } else {
                    *(float2*)(g.Cf + (size_t)mr * H + ncol) = make_float2(v0, v1);
                }
            }
        }
    }
}

// ======================= persistent layer-1 GEMM =============================
// One launch, 148 CTAs over 3 jobs (U/I/G). Per CTA: W hi/lo for both terms
// resident in SMEM; 64-row A sub-tiles (per term, hi+lo) streamed via
// cp.async double buffer. C = relu(A0@W0^T + A1@W1^T + bias).
struct LJob {
    const __nv_bfloat16* Ah0; const __nv_bfloat16* Al0;
    const __nv_bfloat16* Ah1; const __nv_bfloat16* Al1;
    const __nv_bfloat16* Wh0; const __nv_bfloat16* Wh1;  // lo plane at +HH
    const float* bias;
    float* Cf;
    __nv_bfloat16* Cb;
    int loOff, M, ntiles, ctaBase, nctas, flags;
};
struct LJob3 { LJob j[3]; };

#define SMEM_GL (4 * TILEB + 4 * HTILE)   // 208896

__device__ __forceinline__ void loadA64(uint32_t dst, const uint4* ah, const uint4* al,
                                        int m0_, int M, int tid)
{
#pragma unroll 2
    for (int i = tid; i < 1024; i += 256) {
        int row = i >> 4, cq = i & 15;
        int gr = m0_ + row;
        int sz = (gr < M) ? 16 : 0;
        if (gr >= M) gr = M - 1;
        uint32_t so = dst + (uint32_t)row * ROWB + cq * 16;
        CPA16(so,         ah + (size_t)gr * 16 + cq, sz);
        CPA16(so + HTILE, al + (size_t)gr * 16 + cq, sz);
    }
}

__global__ void __launch_bounds__(256, 1)
k_gemm_l(LJob3 js)
{
    extern __shared__ char sm[];
    const int tid  = threadIdx.x;
    const int wid  = tid >> 5;
    const int lane = tid & 31;
    const int wm   = wid >> 2;            // 0..1 (32 M-rows each)
    const int wn   = wid & 3;             // 0..3 (32 N-cols each)

    int ji = (blockIdx.x >= (uint32_t)js.j[2].ctaBase) ? 2
           : (blockIdx.x >= (uint32_t)js.j[1].ctaBase) ? 1 : 0;
    const LJob g = js.j[ji];
    const int idx = blockIdx.x - g.ctaBase;
    const int beg = (int)((long long)idx * g.ntiles / g.nctas);
    const int end = (int)((long long)(idx + 1) * g.ntiles / g.nctas);
    if (beg >= end) return;

    const uint32_t sbase = smem_u32(sm);
    const uint32_t sA    = sbase + 4 * TILEB;

    // ---- resident W load: 4 tiles (t0 hi, t0 lo, t1 hi, t1 lo) ----
    {
        const uint4* wsrc0 = (const uint4*)g.Wh0;
        const uint4* wsrc1 = (const uint4*)(g.Wh0 + HH);
        const uint4* wsrc2 = (const uint4*)g.Wh1;
        const uint4* wsrc3 = (const uint4*)(g.Wh1 + HH);
#pragma unroll 4
        for (int i = tid; i < 8192; i += 256) {
            int tl = i >> 11;
            int row = (i >> 4) & 127;
            int cq = i & 15;
            const uint4* src = (tl == 0) ? wsrc0 : (tl == 1) ? wsrc1 : (tl == 2) ? wsrc2 : wsrc3;
            CPA16(sbase + (uint32_t)tl * TILEB + (uint32_t)row * ROWB + cq * 16,
                  src + (size_t)row * 16 + cq, 16);
        }
    }
    // first A item (tile beg, term 0) into buf 0
    loadA64(sA, (const uint4*)g.Ah0, (const uint4*)g.Al0, beg * 64, g.M, tid);
    CP_COMMIT();

    const uint32_t a_loff = (uint32_t)(lane & 15) * ROWB + (uint32_t)(lane >> 4) * 16;
    const uint32_t b_loff = (uint32_t)(((lane >> 4) * 8) + (lane & 7)) * ROWB
                          + (uint32_t)((lane >> 3) & 1) * 16;
    const int gid = lane >> 2;
    const int tq  = (lane & 3) * 2;
    const bool relu = (g.flags & GEMM_RELU) != 0;
    const bool bfo  = (g.flags & GEMM_BF16) != 0;

    float c[2][4][4];
    const int nit = (end - beg) * 2;
    int buf = 0;

#pragma unroll 1
    for (int it = 0; it < nit; it++) {
        const int tile = beg + (it >> 1);
        const int term = it & 1;
        // prefetch next item into other buffer
        if (it + 1 < nit) {
            int ntile = beg + ((it + 1) >> 1);
            int nterm = (it + 1) & 1;
            const uint4* ah = (const uint4*)(nterm ? g.Ah1 : g.Ah0);
            const uint4* al = (const uint4*)(nterm ? g.Al1 : g.Al0);
            loadA64(sA + (uint32_t)(buf ^ 1) * 2 * HTILE, ah, al, ntile * 64, g.M, tid);
            CP_COMMIT();
            CP_WAIT1();
        } else {
            CP_WAIT0();
        }
        __syncthreads();

        if (term == 0) {
#pragma unroll
            for (int i = 0; i < 2; i++)
#pragma unroll
                for (int j = 0; j < 4; j++)
#pragma unroll
                    for (int q = 0; q < 4; q++) c[i][j][q] = 0.f;
        }

        const uint32_t curA = sA + (uint32_t)buf * 2 * HTILE;
        const uint32_t wBase = sbase + (uint32_t)term * 2 * TILEB;
#pragma unroll 1
        for (int sp = 0; sp < 3; sp++) {
            uint32_t aB = curA + (sp == 2 ? HTILE : 0) + (uint32_t)wm * 32 * ROWB + a_loff;
            uint32_t bB = wBase + (sp == 1 ? TILEB : 0) + (uint32_t)wn * 32 * ROWB + b_loff;
#pragma unroll
            for (int ks = 0; ks < 8; ks++) {
                uint32_t a[2][4], b[2][4];
                LDSM4(a[0], aB + ks * 32);
                LDSM4(a[1], aB + ks * 32 + 16 * ROWB);
                LDSM4(b[0], bB + ks * 32);
                LDSM4(b[1], bB + ks * 32 + 16 * ROWB);
#pragma unroll
                for (int ma = 0; ma < 2; ma++)
#pragma unroll
                    for (int na = 0; na < 4; na++)
                        MMA_BF16(c[ma][na], a[ma],
                                 b[na >> 1][(na & 1) * 2], b[na >> 1][(na & 1) * 2 + 1]);
            }
        }

        if (term == 1) {
            int m0_ = tile * 64;
#pragma unroll
            for (int ma = 0; ma < 2; ma++) {
#pragma unroll
                for (int na = 0; na < 4; na++) {
                    int mrow = m0_ + wm * 32 + ma * 16 + gid;
                    int ncol = wn * 32 + na * 8 + tq;
                    float2 bv = *(const float2*)(g.bias + ncol);
#pragma unroll
                    for (int hrow = 0; hrow < 2; hrow++) {
                        int mr = mrow + hrow * 8;
                        if (mr >= g.M) continue;
                        float v0 = c[ma][na][hrow*2 + 0] + bv.x;
                        float v1 = c[ma][na][hrow*2 + 1] + bv.y;
                        if (relu) { v0 = fmaxf(v0, 0.f); v1 = fmaxf(v1, 0.f); }
                        if (bfo) {
                            uint32_t hw, lw;
                            bfsplit2(v0, v1, hw, lw);
                            *(uint32_t*)(g.Cb + (size_t)mr * H + ncol) = hw;
                            *(uint32_t*)(g.Cb + (size_t)g.loOff + (size_t)mr * H + ncol) = lw;
                        } else {
                            *(float2*)(g.Cf + (size_t)mr * H + ncol) = make_float2(v0, v1);
                        }
                    }
                }
            }
        }
        __syncthreads();
        buf ^= 1;
    }
}

// ======================= persistent pred GEMM ================================
#define NTN ((NI + 127) / 128)    // 157
#define NTM ((NG + 127) / 128)    // 40
#define NT_TOT (NTN * NTM)        // 6280
#define NCTA_PRED 148
#define SMEM_PRED (6 * TILEB)     // 208896

__device__ __forceinline__ void pred_loadA(uint32_t dstA, const uint4* gh, const uint4* gl,
                                           int m0_, int tid)
{
#pragma unroll 4
    for (int i = tid; i < 2048; i += 256) {
        int row = i >> 4, cq = i & 15;
        int gr = m0_ + row;
        int sz = (gr < NG) ? 16 : 0;
        if (gr >= NG) gr = NG - 1;
        uint32_t so = dstA + (uint32_t)row * ROWB + cq * 16;
        CPA16(so,         gh + (size_t)gr * 16 + cq, sz);
        CPA16(so + TILEB, gl + (size_t)gr * 16 + cq, sz);
    }
}

__device__ __forceinline__ void pred_loadB(uint32_t dstB, const uint4* gh, const uint4* gl,
                                           int n0_, int tid)
{
#pragma unroll 4
    for (int i = tid; i < 2048; i += 256) {
        int row = i >> 4, cq = i & 15;
        int gr = n0_ + row;
        int sz = (gr < NI) ? 16 : 0;
        if (gr >= NI) gr = NI - 1;
        uint32_t so = dstB + (uint32_t)row * ROWB + cq * 16;
        CPA16(so,         gh + (size_t)gr * 16 + cq, sz);
        CPA16(so + TILEB, gl + (size_t)gr * 16 + cq, sz);
    }
}

__global__ void __launch_bounds__(256, 1)
k_mma_pred(const __nv_bfloat16* __restrict__ Ahi, const __nv_bfloat16* __restrict__ Alo,
           const __nv_bfloat16* __restrict__ Bhi, const __nv_bfloat16* __restrict__ Blo,
           const float* __restrict__ bias, float* __restrict__ out)
{
    extern __shared__ char sm[];
    const int tid  = threadIdx.x;
    const int wid  = tid >> 5;
    const int lane = tid & 31;
    const int wm   = wid >> 1;
    const int wn   = wid & 1;

    const uint32_t sbase = smem_u32(sm);
    const uint32_t sB    = sbase + 2 * TILEB;

    const uint4* gAh = (const uint4*)Ahi;
    const uint4* gAl = (const uint4*)Alo;
    const uint4* gBh = (const uint4*)Bhi;
    const uint4* gBl = (const uint4*)Blo;

    const int beg = (int)((long long)blockIdx.x * NT_TOT / NCTA_PRED);
    const int end = (int)((long long)(blockIdx.x + 1) * NT_TOT / NCTA_PRED);

    const uint32_t a_loff = (uint32_t)(lane & 15) * ROWB + (uint32_t)(lane >> 4) * 16;
    const uint32_t b_loff = (uint32_t)(((lane >> 4) * 8) + (lane & 7)) * ROWB
                          + (uint32_t)((lane >> 3) & 1) * 16;
    const int gid = lane >> 2;
    const int tq  = (lane & 3) * 2;

    int cur_m = -1;
    int buf = 0;

#pragma unroll 1
    for (int t = beg; t < end; ++t) {
        int tm = t / NTN, tn = t - tm * NTN;
        if (tm != cur_m) {
            CP_WAIT0();
            __syncthreads();
            pred_loadA(sbase, gAh, gAl, tm * 128, tid);
            pred_loadB(sB, gBh, gBl, tn * 128, tid);
            CP_COMMIT();
            cur_m = tm;
            buf = 0;
            if (t + 1 < end && (t + 1) / NTN == cur_m) {
                pred_loadB(sB + 2 * TILEB, gBh, gBl, (tn + 1) * 128, tid);
                CP_COMMIT();
                CP_WAIT1();
            } else {
                CP_WAIT0();
            }
            __syncthreads();
        } else {
            if (t + 1 < end && (t + 1) / NTN == cur_m) {
                pred_loadB(sB + (uint32_t)(buf ^ 1) * 2 * TILEB, gBh, gBl, (tn + 1) * 128, tid);
                CP_COMMIT();
                CP_WAIT1();
            } else {
                CP_WAIT0();
            }
            __syncthreads();
        }

        float c[2][8][4];
#pragma unroll
        for (int i = 0; i < 2; i++)
#pragma unroll
            for (int j = 0; j < 8; j++)
#pragma unroll
                for (int q = 0; q < 4; q++) c[i][j][q] = 0.f;

        uint32_t curB = sB + (uint32_t)buf * 2 * TILEB;
#pragma unroll 1
        for (int sp = 0; sp < 3; sp++) {
            uint32_t aB = sbase + (sp == 2 ? TILEB : 0) + (uint32_t)wm * 32 * ROWB + a_loff;
            uint32_t bB = curB + (sp == 1 ? TILEB : 0) + (uint32_t)wn * 64 * ROWB + b_loff;
#pragma unroll
            for (int ks = 0; ks < 8; ks++) {
                uint32_t a[2][4], b[4][4];
                LDSM4(a[0], aB + ks * 32);
                LDSM4(a[1], aB + ks * 32 + 16 * ROWB);
#pragma unroll
                for (int q = 0; q < 4; q++)
                    LDSM4(b[q], bB + ks * 32 + q * 16 * ROWB);
#pragma unroll
                for (int ma = 0; ma < 2; ma++)
#pragma unroll
                    for (int na = 0; na < 8; na++)
                        MMA_BF16(c[ma][na], a[ma],
                                 b[na >> 1][(na & 1) * 2], b[na >> 1][(na & 1) * 2 + 1]);
            }
        }

        int m0_ = tm * 128, n0_ = tn * 128;
#pragma unroll
        for (int ma = 0; ma < 2; ma++) {
#pragma unroll
            for (int na = 0; na < 8; na++) {
                int mrow = m0_ + wm * 32 + ma * 16 + gid;
                int ncol = n0_ + wn * 64 + na * 8 + tq;
                if (ncol >= NI) continue;
                float2 bv = *(const float2*)(bias + ncol);
                if (mrow < NG) {
                    float2 v = make_float2(c[ma][na][0] + bv.x, c[ma][na][1] + bv.y);
                    *(float2*)(out + (size_t)mrow * NI + ncol) = v;
                }
                if (mrow + 8 < NG) {
                    float2 v = make_float2(c[ma][na][2] + bv.x, c[ma][na][3] + bv.y);
                    *(float2*)(out + (size_t)(mrow + 8) * NI + ncol) = v;
                }
            }
        }
        __syncthreads();
        buf ^= 1;
    }
}

// ---------------------------------------------------------------------------
extern "C" void kernel_launch(void* const* d_in, const int* in_sizes, int n_in,
                              void* d_out, int out_size)
{
    const int*   x_user   = (const int*)  d_in[1];
    const int*   x_item   = (const int*)  d_in[2];
    const float* emb_user = (const float*)d_in[4];
    const float* emb_item = (const float*)d_in[5];
    const float* W1l      = (const float*)d_in[6];
    const float* W1r      = (const float*)d_in[7];
    const float* b1       = (const float*)d_in[8];
    const float* W2l      = (const float*)d_in[9];
    const float* W2r      = (const float*)d_in[10];
    const float* b2       = (const float*)d_in[11];
    const float* pred_W   = (const float*)d_in[12];
    const float* pred_b   = (const float*)d_in[13];
    const int*   ug_src   = (const int*)  d_in[14];
    const int*   ug_dst   = (const int*)  d_in[15];
    const int*   ui_src   = (const int*)  d_in[16];
    const int*   ui_dst   = (const int*)  d_in[17];
    const int*   gi_src   = (const int*)  d_in[18];
    const int*   gi_dst   = (const int*)  d_in[19];
    float* out = (float*)d_out;

    float* fb = nullptr; int* ib = nullptr; __nv_bfloat16* bb = nullptr;
    cudaGetSymbolAddress((void**)&fb, g_f);
    cudaGetSymbolAddress((void**)&ib, g_i);
    cudaGetSymbolAddress((void**)&bb, g_bf);

    cudaFuncSetAttribute(k_gemm_h, cudaFuncAttributeMaxDynamicSharedMemorySize, SMEM_GH);
    cudaFuncSetAttribute(k_gemm_l, cudaFuncAttributeMaxDynamicSharedMemorySize, SMEM_GL);
    cudaFuncSetAttribute(k_mma_pred, cudaFuncAttributeMaxDynamicSharedMemorySize, SMEM_PRED);

    cudaMemsetAsync(ib + OI_CNT_G1, 0, (size_t)CNT_TOTAL * sizeof(int));

    // weight prep
    k_splitB<<<dim3(NI / 32, H / 32), dim3(32, 8)>>>(pred_W, bb + OB_PW, bb + OB_PW + NI*H);
    k_wcomb<<<(HH + 255) / 256, 256>>>(W1r, b1, W2r, b2);
    k_splitW<<<dim3(4, 4, 9), dim3(32, 8)>>>(W1l, W2l, fb + OF_WC, bb + OB_W);

    // merged embedding gathers (fp32 + bf16 hi/lo)
    k_gather2m<<<((NU + NI) * 32 + 255) / 256, 256>>>(emb_user, x_user, emb_item, x_item,
                                                      fb, bb);

    // CSR build
    {
        int tot = E_UG + E_GI + 2 * E_UI;
        k_count_all<<<(tot + 255) / 256, 256>>>(ug_dst, gi_src, ui_src, ui_dst, ib);
        k_scan4<<<4, 1024>>>(ib);
        k_bucket_all<<<(tot + 255) / 256, 256>>>(ug_src, ug_dst, ui_src, ui_dst,
                                                 gi_src, gi_dst, ib);
    }

    // layer-1 aggregations -> bf16 hi/lo
    {
        int warps = NU + NI + 2 * NG;
        k_agg_all<<<(warps + 7) / 8, 256>>>(ib, fb, bb);
    }

    // layer-1 GEMMs: one persistent launch, 3 jobs
    {
        LJob3 js;
        // job U: 1563 tiles, CTAs [0,118)
        js.j[0].Ah0 = bb + OB_AIU;  js.j[0].Al0 = bb + OB_AIU + NU*H;
        js.j[0].Ah1 = bb + OB_HUe;  js.j[0].Al1 = bb + OB_HUe + NU*H;
        js.j[0].Wh0 = bb + OB_W + SL_W1L3*2*HH;
        js.j[0].Wh1 = bb + OB_W + SL_WC0*2*HH;
        js.j[0].bias = fb + OF_BC + 0*H;
        js.j[0].Cf = fb + OF_HU1; js.j[0].Cb = nullptr; js.j[0].loOff = 0;
        js.j[0].M = NU; js.j[0].ntiles = (NU + 63) / 64;
        js.j[0].ctaBase = 0;   js.j[0].nctas = 118; js.j[0].flags = GEMM_RELU;
        // job I: 313 tiles, CTAs [118,142)
        js.j[1].Ah0 = bb + OB_AUI;  js.j[1].Al0 = bb + OB_AUI + NI*H;
        js.j[1].Ah1 = bb + OB_HIe;  js.j[1].Al1 = bb + OB_HIe + NI*H;
        js.j[1].Wh0 = bb + OB_W + SL_W1L2*2*HH;
        js.j[1].Wh1 = bb + OB_W + SL_WC1*2*HH;
        js.j[1].bias = fb + OF_BC + 1*H;
        js.j[1].Cf = fb + OF_HI1; js.j[1].Cb = nullptr; js.j[1].loOff = 0;
        js.j[1].M = NI; js.j[1].ntiles = (NI + 63) / 64;
        js.j[1].ctaBase = 118; js.j[1].nctas = 24; js.j[1].flags = GEMM_RELU;
        // job G: 79 tiles, CTAs [142,148)
        js.j[2].Ah0 = bb + OB_AUG;  js.j[2].Al0 = bb + OB_AUG + NG*H;
        js.j[2].Ah1 = bb + OB_AIG;  js.j[2].Al1 = bb + OB_AIG + NG*H;
        js.j[2].Wh0 = bb + OB_W + SL_W1L0*2*HH;
        js.j[2].Wh1 = bb + OB_W + SL_W1L5*2*HH;
        js.j[2].bias = fb + OF_BC + 2*H;
        js.j[2].Cf = nullptr; js.j[2].Cb = bb + OB_HG1; js.j[2].loOff = NG*H;
        js.j[2].M = NG; js.j[2].ntiles = (NG + 63) / 64;
        js.j[2].ctaBase = 142; js.j[2].nctas = 6; js.j[2].flags = GEMM_RELU | GEMM_BF16;
        k_gemm_l<<<148, 256, SMEM_GL>>>(js);
    }

    // layer-2 aggregations
    k_agg_all2<<<(2 * NG + 7) / 8, 256>>>(ib, fb, bb);

    // layer-2 group GEMM (3 terms) -> REP bf16 hi/lo
    {
        GemmArgs a = {};
        a.Ah[0] = bb + OB_BUG;  a.Al[0] = bb + OB_BUG + NG*H;  a.Wh[0] = bb + OB_W + SL_W2L0*2*HH;
        a.Ah[1] = bb + OB_HG1;  a.Al[1] = bb + OB_HG1 + NG*H;  a.Wh[1] = bb + OB_W + SL_WC2*2*HH;
        a.Ah[2] = bb + OB_BIG;  a.Al[2] = bb + OB_BIG + NG*H;  a.Wh[2] = bb + OB_W + SL_W2L5*2*HH;
        a.bias = fb + OF_BC + 3*H;
        a.Cb = bb + OB_REP; a.loOff = NG*H;
        a.M = NG; a.nterms = 3; a.flags = GEMM_RELU | GEMM_BF16;
        k_gemm_h<<<(NG + 127) / 128, 256, SMEM_GH>>>(a);
    }

    // persistent prediction GEMM
    k_mma_pred<<<NCTA_PRED, 256, SMEM_PRED>>>(bb + OB_REP, bb + OB_REP + NG*H,
                                              bb + OB_PW,  bb + OB_PW + NI*H,
                                              pred_b, out);
    (void)in_sizes; (void)n_in; (void)out_size;
}